// round 1
// baseline (speedup 1.0000x reference)
#include <cuda_runtime.h>
#include <cuda_bf16.h>
#include <math.h>
#include <float.h>

// Problem constants
#define T_   4096      // B*S tokens
#define H_   2048
#define S_   2048
#define NH_  16
#define HD_  128
#define E_   8
#define I_   2048
#define EPS_ 1e-5f
#define SCALE_ 0.08838834764831845f  // 1/sqrt(128)

// ---------------- scratch (static device globals; no allocations) ----------
__device__ float g_xn [T_ * H_];       // rmsnorm output (reused for both norms)
__device__ float g_q  [T_ * H_];
__device__ float g_k  [T_ * H_];
__device__ float g_v  [T_ * H_];
__device__ float g_ctx[T_ * H_];
__device__ float g_h1 [T_ * H_];       // residual after attention
__device__ float g_a1 [2 * T_ * I_];   // expert up-proj (w1) / fused act
__device__ float g_a3 [2 * T_ * I_];   // expert up-proj (w3)
__device__ int   g_cnt [E_];
__device__ int   g_tok [E_ * T_];      // token index per expert slot
__device__ int   g_aid [E_ * T_];      // assignment id (t*2 + rank) per slot
__device__ float g_coef[E_ * T_];      // routing coefficient per slot

// ---------------- rmsnorm (+ optional residual copy into d_out) ------------
__global__ void rmsnorm_kernel(const float* __restrict__ x, const float* __restrict__ w,
                               float* __restrict__ out, float* __restrict__ cpy)
{
    const int t   = blockIdx.x;
    const int tid = threadIdx.x;                  // 256 threads, 8 elems each
    const float* xr = x + (size_t)t * H_;
    float4 v0 = *(const float4*)(xr + tid * 4);
    float4 v1 = *(const float4*)(xr + 1024 + tid * 4);
    float ss = v0.x*v0.x + v0.y*v0.y + v0.z*v0.z + v0.w*v0.w
             + v1.x*v1.x + v1.y*v1.y + v1.z*v1.z + v1.w*v1.w;
#pragma unroll
    for (int o = 16; o > 0; o >>= 1) ss += __shfl_down_sync(0xffffffffu, ss, o);
    __shared__ float wsum[8];
    __shared__ float rsh;
    if ((tid & 31) == 0) wsum[tid >> 5] = ss;
    __syncthreads();
    if (tid == 0) {
        float tot = 0.f;
#pragma unroll
        for (int i = 0; i < 8; i++) tot += wsum[i];
        rsh = rsqrtf(tot * (1.f / H_) + EPS_);
    }
    __syncthreads();
    const float r = rsh;
    float4 w0 = *(const float4*)(w + tid * 4);
    float4 w1 = *(const float4*)(w + 1024 + tid * 4);
    float4 o0 = make_float4(v0.x*r*w0.x, v0.y*r*w0.y, v0.z*r*w0.z, v0.w*r*w0.w);
    float4 o1 = make_float4(v1.x*r*w1.x, v1.y*r*w1.y, v1.z*r*w1.z, v1.w*r*w1.w);
    float* op = out + (size_t)t * H_;
    *(float4*)(op + tid * 4)        = o0;
    *(float4*)(op + 1024 + tid * 4) = o1;
    if (cpy) {
        float* cp = cpy + (size_t)t * H_;
        *(float4*)(cp + tid * 4)        = v0;
        *(float4*)(cp + 1024 + tid * 4) = v1;
    }
}

// ---------------- dense SGEMM: C[M,N] = A[M,K] @ B[K,N] (+ addend) ---------
// 128x128 block tile, BK=8, 256 threads, 8x8 per thread. M,N,K multiples of 128/8.
__global__ void sgemm_dense(const float* __restrict__ A, const float* __restrict__ B,
                            float* __restrict__ C, const float* __restrict__ addend,
                            int M, int N, int K)
{
    __shared__ float As[8][128];
    __shared__ float Bs[8][128];
    const int tid = threadIdx.x;
    const int n0 = blockIdx.x * 128;
    const int m0 = blockIdx.y * 128;
    const int tr = tid >> 4, tc = tid & 15;
    const int aRow = tid >> 1,  aCol = (tid & 1) << 2;
    const int bRow = tid >> 5,  bCol = (tid & 31) << 2;
    const float* Ap = A + (size_t)(m0 + aRow) * K + aCol;
    const float* Bp = B + (size_t)bRow * N + n0 + bCol;

    float acc[8][8];
#pragma unroll
    for (int i = 0; i < 8; i++)
#pragma unroll
        for (int j = 0; j < 8; j++) acc[i][j] = 0.f;

    for (int k0 = 0; k0 < K; k0 += 8) {
        float4 av = *(const float4*)(Ap + k0);
        float4 bv = *(const float4*)(Bp + (size_t)k0 * N);
        __syncthreads();
        As[aCol + 0][aRow] = av.x;
        As[aCol + 1][aRow] = av.y;
        As[aCol + 2][aRow] = av.z;
        As[aCol + 3][aRow] = av.w;
        *(float4*)&Bs[bRow][bCol] = bv;
        __syncthreads();
#pragma unroll
        for (int kk = 0; kk < 8; kk++) {
            float4 a0 = *(const float4*)&As[kk][tr * 8];
            float4 a1 = *(const float4*)&As[kk][tr * 8 + 4];
            float4 b0 = *(const float4*)&Bs[kk][tc * 8];
            float4 b1 = *(const float4*)&Bs[kk][tc * 8 + 4];
            float ar[8] = {a0.x,a0.y,a0.z,a0.w,a1.x,a1.y,a1.z,a1.w};
            float br[8] = {b0.x,b0.y,b0.z,b0.w,b1.x,b1.y,b1.z,b1.w};
#pragma unroll
            for (int i = 0; i < 8; i++)
#pragma unroll
                for (int j = 0; j < 8; j++) acc[i][j] += ar[i] * br[j];
        }
    }
#pragma unroll
    for (int i = 0; i < 8; i++) {
        const int r = m0 + tr * 8 + i;
        float* cp = C + (size_t)r * N + n0 + tc * 8;
        if (addend) {
            const float* dp = addend + (size_t)r * N + n0 + tc * 8;
            float4 d0 = *(const float4*)dp, d1 = *(const float4*)(dp + 4);
            *(float4*)cp       = make_float4(acc[i][0]+d0.x, acc[i][1]+d0.y, acc[i][2]+d0.z, acc[i][3]+d0.w);
            *(float4*)(cp + 4) = make_float4(acc[i][4]+d1.x, acc[i][5]+d1.y, acc[i][6]+d1.z, acc[i][7]+d1.w);
        } else {
            *(float4*)cp       = make_float4(acc[i][0], acc[i][1], acc[i][2], acc[i][3]);
            *(float4*)(cp + 4) = make_float4(acc[i][4], acc[i][5], acc[i][6], acc[i][7]);
        }
    }
}

// ------------- gathered/scattered expert SGEMM (blockIdx.z = expert) -------
__global__ void sgemm_expert(const float* __restrict__ Abase, const float* __restrict__ Bbase,
                             float* __restrict__ Cbase,
                             const int* __restrict__ counts,
                             const int* __restrict__ arow_l, const int* __restrict__ crow_l,
                             const float* __restrict__ cscale, int doAtomic,
                             int N, int K)
{
    const int e   = blockIdx.z;
    const int cnt = counts[e];
    const int m0  = blockIdx.y * 128;
    if (m0 >= cnt) return;
    const float* B  = Bbase + (size_t)e * K * N;
    const int*   ar = arow_l + e * T_;
    const int*   cr = crow_l + e * T_;

    __shared__ float As[8][128];
    __shared__ float Bs[8][128];
    const int tid = threadIdx.x;
    const int n0 = blockIdx.x * 128;
    const int tr = tid >> 4, tc = tid & 15;
    const int aRow = tid >> 1,  aCol = (tid & 1) << 2;
    const int bRow = tid >> 5,  bCol = (tid & 31) << 2;

    const int aR = m0 + aRow;
    const float* Ap = (aR < cnt) ? (Abase + (size_t)ar[aR] * K + aCol) : nullptr;
    const float* Bp = B + (size_t)bRow * N + n0 + bCol;

    float acc[8][8];
#pragma unroll
    for (int i = 0; i < 8; i++)
#pragma unroll
        for (int j = 0; j < 8; j++) acc[i][j] = 0.f;

    for (int k0 = 0; k0 < K; k0 += 8) {
        float4 av = Ap ? *(const float4*)(Ap + k0) : make_float4(0.f,0.f,0.f,0.f);
        float4 bv = *(const float4*)(Bp + (size_t)k0 * N);
        __syncthreads();
        As[aCol + 0][aRow] = av.x;
        As[aCol + 1][aRow] = av.y;
        As[aCol + 2][aRow] = av.z;
        As[aCol + 3][aRow] = av.w;
        *(float4*)&Bs[bRow][bCol] = bv;
        __syncthreads();
#pragma unroll
        for (int kk = 0; kk < 8; kk++) {
            float4 a0 = *(const float4*)&As[kk][tr * 8];
            float4 a1 = *(const float4*)&As[kk][tr * 8 + 4];
            float4 b0 = *(const float4*)&Bs[kk][tc * 8];
            float4 b1 = *(const float4*)&Bs[kk][tc * 8 + 4];
            float arr[8] = {a0.x,a0.y,a0.z,a0.w,a1.x,a1.y,a1.z,a1.w};
            float brr[8] = {b0.x,b0.y,b0.z,b0.w,b1.x,b1.y,b1.z,b1.w};
#pragma unroll
            for (int i = 0; i < 8; i++)
#pragma unroll
                for (int j = 0; j < 8; j++) acc[i][j] += arr[i] * brr[j];
        }
    }
#pragma unroll
    for (int i = 0; i < 8; i++) {
        const int r = m0 + tr * 8 + i;
        if (r >= cnt) continue;
        const int orow = cr[r];
        float* cp = Cbase + (size_t)orow * N + n0 + tc * 8;
        if (doAtomic) {
            const float s = cscale[e * T_ + r];
#pragma unroll
            for (int j = 0; j < 8; j++) atomicAdd(cp + j, s * acc[i][j]);
        } else {
            *(float4*)cp       = make_float4(acc[i][0], acc[i][1], acc[i][2], acc[i][3]);
            *(float4*)(cp + 4) = make_float4(acc[i][4], acc[i][5], acc[i][6], acc[i][7]);
        }
    }
}

// ---------------- RoPE (in-place on q and k) -------------------------------
__global__ void rope_kernel(float* __restrict__ q, float* __restrict__ k,
                            const int* __restrict__ pos_ids)
{
    const int idx = blockIdx.x * blockDim.x + threadIdx.x;   // T*NH*64
    if (idx >= T_ * NH_ * 64) return;
    const int d  = idx & 63;
    const int hh = (idx >> 6) & (NH_ - 1);
    const int t  = idx >> 10;
    const float pos = (float)pos_ids[t];
    // inv_freq = 10000^{-d/64} = exp(-d * ln(10000)/64)
    const float inv = expf(-0.14391156831212787f * (float)d);
    float sv, cv;
    sincosf(pos * inv, &sv, &cv);
    const size_t base = (size_t)t * H_ + hh * HD_ + d;
    float q1 = q[base], q2 = q[base + 64];
    q[base]      = q1 * cv - q2 * sv;
    q[base + 64] = q2 * cv + q1 * sv;
    float k1 = k[base], k2 = k[base + 64];
    k[base]      = k1 * cv - k2 * sv;
    k[base + 64] = k2 * cv + k1 * sv;
}

// ---------------- causal flash attention (fp32, Br=Bc=64, 512 threads) -----
#define FLASH_SMEM ((64*128 + 64*132 + 64*128 + 64*68) * 4)

__global__ void flash_kernel(const float* __restrict__ q, const float* __restrict__ k,
                             const float* __restrict__ v, float* __restrict__ ctx)
{
    extern __shared__ float sm[];
    float* Qs = sm;                     // [64][128]
    float* Ks = Qs + 64 * 128;          // [64][132] (pad 4)
    float* Vs = Ks + 64 * 132;          // [64][128]
    float* Ss = Vs + 64 * 128;          // [64][68]  (pad 4)

    const int qt = blockIdx.x, hh = blockIdx.y, b = blockIdx.z;
    const int tid = threadIdx.x;        // 512

    const size_t qbase = ((size_t)(b * S_ + qt * 64)) * H_ + hh * HD_;
#pragma unroll
    for (int g = 0; g < 4; g++) {
        const int gid = g * 512 + tid;
        const int r = gid >> 5, c4 = (gid & 31) << 2;
        *(float4*)&Qs[r * 128 + c4] = *(const float4*)(q + qbase + (size_t)r * H_ + c4);
    }

    const int row = tid >> 3, part = tid & 7;     // PV partition: 64 rows x 8 parts
    const int sy  = tid >> 4, sx  = tid & 15;     // S partition: 32x16, 2x4 per thread
    float m_i = -FLT_MAX, l_i = 0.f;
    float acc[16];
#pragma unroll
    for (int c = 0; c < 16; c++) acc[c] = 0.f;

    for (int kc = 0; kc <= qt; kc++) {
        __syncthreads();   // previous tile fully consumed (also covers Q load)
        const size_t kbase = ((size_t)(b * S_ + kc * 64)) * H_ + hh * HD_;
#pragma unroll
        for (int g = 0; g < 4; g++) {
            const int gid = g * 512 + tid;
            const int r = gid >> 5, c4 = (gid & 31) << 2;
            *(float4*)&Ks[r * 132 + c4] = *(const float4*)(k + kbase + (size_t)r * H_ + c4);
            *(float4*)&Vs[r * 128 + c4] = *(const float4*)(v + kbase + (size_t)r * H_ + c4);
        }
        __syncthreads();

        // S tile = Q K^T (each thread: 2 rows x 4 cols)
        float cc[2][4];
#pragma unroll
        for (int i = 0; i < 2; i++)
#pragma unroll
            for (int j = 0; j < 4; j++) cc[i][j] = 0.f;
        const float* qp0 = &Qs[(2 * sy) * 128];
        const float* qp1 = qp0 + 128;
#pragma unroll 8
        for (int k4 = 0; k4 < 32; k4++) {
            float4 a0 = *(const float4*)(qp0 + 4 * k4);
            float4 a1 = *(const float4*)(qp1 + 4 * k4);
#pragma unroll
            for (int j = 0; j < 4; j++) {
                float4 bb = *(const float4*)&Ks[(4 * sx + j) * 132 + 4 * k4];
                cc[0][j] += a0.x*bb.x + a0.y*bb.y + a0.z*bb.z + a0.w*bb.w;
                cc[1][j] += a1.x*bb.x + a1.y*bb.y + a1.z*bb.z + a1.w*bb.w;
            }
        }
        const bool diag = (kc == qt);
#pragma unroll
        for (int i = 0; i < 2; i++)
#pragma unroll
            for (int j = 0; j < 4; j++) {
                const int rr = 2 * sy + i, cl = 4 * sx + j;
                float val = cc[i][j] * SCALE_;
                if (diag && cl > rr) val = -1e30f;
                Ss[rr * 68 + cl] = val;
            }
        __syncthreads();

        // online softmax + P*V (each thread: 1 row, 16 contiguous output cols)
        const float* srow = &Ss[row * 68];
        float mx = m_i;
#pragma unroll 16
        for (int j = 0; j < 64; j++) mx = fmaxf(mx, srow[j]);
        const float alpha = __expf(m_i - mx);
        m_i = mx;
        l_i *= alpha;
#pragma unroll
        for (int c = 0; c < 16; c++) acc[c] *= alpha;
        const float* vp = &Vs[part * 16];
#pragma unroll 4
        for (int j = 0; j < 64; j++) {
            const float p = __expf(srow[j] - mx);
            l_i += p;
            const float* vj = vp + j * 128;
            float4 v0 = *(const float4*)(vj);
            float4 v1 = *(const float4*)(vj + 4);
            float4 v2 = *(const float4*)(vj + 8);
            float4 v3 = *(const float4*)(vj + 12);
            acc[ 0] += p * v0.x; acc[ 1] += p * v0.y; acc[ 2] += p * v0.z; acc[ 3] += p * v0.w;
            acc[ 4] += p * v1.x; acc[ 5] += p * v1.y; acc[ 6] += p * v1.z; acc[ 7] += p * v1.w;
            acc[ 8] += p * v2.x; acc[ 9] += p * v2.y; acc[10] += p * v2.z; acc[11] += p * v2.w;
            acc[12] += p * v3.x; acc[13] += p * v3.y; acc[14] += p * v3.z; acc[15] += p * v3.w;
        }
    }

    const float invl = 1.f / l_i;
    float* op = ctx + ((size_t)(b * S_ + qt * 64 + row)) * H_ + hh * HD_ + part * 16;
    *(float4*)(op + 0)  = make_float4(acc[0]*invl,  acc[1]*invl,  acc[2]*invl,  acc[3]*invl);
    *(float4*)(op + 4)  = make_float4(acc[4]*invl,  acc[5]*invl,  acc[6]*invl,  acc[7]*invl);
    *(float4*)(op + 8)  = make_float4(acc[8]*invl,  acc[9]*invl,  acc[10]*invl, acc[11]*invl);
    *(float4*)(op + 12) = make_float4(acc[12]*invl, acc[13]*invl, acc[14]*invl, acc[15]*invl);
}

// ---------------- router: logits -> top2 -> expert lists -------------------
__global__ void zero_counts_kernel(int* c)
{
    if (threadIdx.x < E_) c[threadIdx.x] = 0;
}

__global__ void router_kernel(const float* __restrict__ xn, const float* __restrict__ rw,
                              int* __restrict__ counts, int* __restrict__ tok,
                              int* __restrict__ aid, float* __restrict__ coef)
{
    const int t = blockIdx.x;
    const int tid = threadIdx.x;     // 256
    float a[8] = {0.f,0.f,0.f,0.f,0.f,0.f,0.f,0.f};
    const float* xr = xn + (size_t)t * H_;
    for (int kk = tid; kk < H_; kk += 256) {
        const float xv = xr[kk];
        float4 r0 = *(const float4*)(rw + kk * 8);
        float4 r1 = *(const float4*)(rw + kk * 8 + 4);
        a[0] += xv * r0.x; a[1] += xv * r0.y; a[2] += xv * r0.z; a[3] += xv * r0.w;
        a[4] += xv * r1.x; a[5] += xv * r1.y; a[6] += xv * r1.z; a[7] += xv * r1.w;
    }
#pragma unroll
    for (int o = 16; o > 0; o >>= 1)
#pragma unroll
        for (int e = 0; e < 8; e++) a[e] += __shfl_down_sync(0xffffffffu, a[e], o);
    __shared__ float ws[8][8];
    if ((tid & 31) == 0)
#pragma unroll
        for (int e = 0; e < 8; e++) ws[tid >> 5][e] = a[e];
    __syncthreads();
    if (tid == 0) {
        float lg[8];
#pragma unroll
        for (int e = 0; e < 8; e++) {
            float s = 0.f;
#pragma unroll
            for (int w = 0; w < 8; w++) s += ws[w][e];
            lg[e] = s;
        }
        int i1 = 0;
#pragma unroll
        for (int e = 1; e < 8; e++) if (lg[e] > lg[i1]) i1 = e;
        int i2 = (i1 == 0) ? 1 : 0;
#pragma unroll
        for (int e = 0; e < 8; e++) if (e != i1 && lg[e] > lg[i2]) i2 = e;
        const float ex = expf(lg[i2] - lg[i1]);
        const float c1 = 1.f / (1.f + ex);
        const float c2 = ex / (1.f + ex);
        int s1 = atomicAdd(&counts[i1], 1);
        tok[i1 * T_ + s1] = t; aid[i1 * T_ + s1] = 2 * t;     coef[i1 * T_ + s1] = c1;
        int s2 = atomicAdd(&counts[i2], 1);
        tok[i2 * T_ + s2] = t; aid[i2 * T_ + s2] = 2 * t + 1; coef[i2 * T_ + s2] = c2;
    }
}

// ---------------- fused SiLU * gate ----------------------------------------
__global__ void silu_mul_kernel(float4* __restrict__ a1, const float4* __restrict__ a3, int n4)
{
    const int i = blockIdx.x * blockDim.x + threadIdx.x;
    if (i >= n4) return;
    float4 g = a1[i];
    float4 u = a3[i];
    g.x = (g.x / (1.f + __expf(-g.x))) * u.x;
    g.y = (g.y / (1.f + __expf(-g.y))) * u.y;
    g.z = (g.z / (1.f + __expf(-g.z))) * u.z;
    g.w = (g.w / (1.f + __expf(-g.w))) * u.w;
    a1[i] = g;
}

// ---------------- launcher -------------------------------------------------
extern "C" void kernel_launch(void* const* d_in, const int* in_sizes, int n_in,
                              void* d_out, int out_size)
{
    const float* hidden   = (const float*)d_in[0];
    const int*   pos      = (const int*)  d_in[1];
    const float* rms1_w   = (const float*)d_in[2];
    const float* rms2_w   = (const float*)d_in[3];
    const float* q_w      = (const float*)d_in[4];
    const float* k_w      = (const float*)d_in[5];
    const float* v_w      = (const float*)d_in[6];
    const float* o_w      = (const float*)d_in[7];
    const float* router_w = (const float*)d_in[8];
    const float* w1       = (const float*)d_in[9];
    const float* w2       = (const float*)d_in[10];
    const float* w3       = (const float*)d_in[11];
    float* out = (float*)d_out;

    float *xn, *qb, *kb, *vb, *ctx, *h1, *a1, *a3, *coef;
    int *cnt, *tokl, *aidl;
    cudaGetSymbolAddress((void**)&xn,   g_xn);
    cudaGetSymbolAddress((void**)&qb,   g_q);
    cudaGetSymbolAddress((void**)&kb,   g_k);
    cudaGetSymbolAddress((void**)&vb,   g_v);
    cudaGetSymbolAddress((void**)&ctx,  g_ctx);
    cudaGetSymbolAddress((void**)&h1,   g_h1);
    cudaGetSymbolAddress((void**)&a1,   g_a1);
    cudaGetSymbolAddress((void**)&a3,   g_a3);
    cudaGetSymbolAddress((void**)&coef, g_coef);
    cudaGetSymbolAddress((void**)&cnt,  g_cnt);
    cudaGetSymbolAddress((void**)&tokl, g_tok);
    cudaGetSymbolAddress((void**)&aidl, g_aid);

    const dim3 gemmGrid(H_ / 128, T_ / 128);          // (16, 32)
    const dim3 expGrid (H_ / 128, T_ / 128, E_);      // (16, 32, 8)

    // 1. pre-attention rmsnorm
    rmsnorm_kernel<<<T_, 256>>>(hidden, rms1_w, xn, nullptr);
    // 2. Q/K/V projections
    sgemm_dense<<<gemmGrid, 256>>>(xn, q_w, qb, nullptr, T_, H_, H_);
    sgemm_dense<<<gemmGrid, 256>>>(xn, k_w, kb, nullptr, T_, H_, H_);
    sgemm_dense<<<gemmGrid, 256>>>(xn, v_w, vb, nullptr, T_, H_, H_);
    // 3. RoPE in place
    rope_kernel<<<(T_ * NH_ * 64) / 256, 256>>>(qb, kb, pos);
    // 4. causal flash attention
    cudaFuncSetAttribute(flash_kernel, cudaFuncAttributeMaxDynamicSharedMemorySize, FLASH_SMEM);
    flash_kernel<<<dim3(S_ / 64, NH_, 2), 512, FLASH_SMEM>>>(qb, kb, vb, ctx);
    // 5. O projection + residual
    sgemm_dense<<<gemmGrid, 256>>>(ctx, o_w, h1, hidden, T_, H_, H_);
    // 6. post-attention rmsnorm; also seed d_out with residual h1
    rmsnorm_kernel<<<T_, 256>>>(h1, rms2_w, xn, out);
    // 7. routing
    zero_counts_kernel<<<1, 32>>>(cnt);
    router_kernel<<<T_, 256>>>(xn, router_w, cnt, tokl, aidl, coef);
    // 8. expert up-projections (gathered rows)
    sgemm_expert<<<expGrid, 256>>>(xn, w1, a1, cnt, tokl, aidl, nullptr, 0, I_, H_);
    sgemm_expert<<<expGrid, 256>>>(xn, w3, a3, cnt, tokl, aidl, nullptr, 0, I_, H_);
    // 9. fused activation
    silu_mul_kernel<<<(2 * T_ * I_ / 4 + 255) / 256, 256>>>((float4*)a1, (const float4*)a3,
                                                            2 * T_ * I_ / 4);
    // 10. down projection, scatter-add coeff * result into out (= h1 + moe)
    sgemm_expert<<<expGrid, 256>>>(a1, w2, out, cnt, aidl, tokl, coef, 1, H_, I_);
}

// round 2
// speedup vs baseline: 1.7802x; 1.7802x over previous
#include <cuda_runtime.h>
#include <math.h>
#include <float.h>

// Problem constants
#define T_   4096      // B*S tokens
#define H_   2048
#define S_   2048
#define NH_  16
#define HD_  128
#define E_   8
#define I_   2048
#define EPS_ 1e-5f
#define SCALE_ 0.08838834764831845f  // 1/sqrt(128)

// ---------------- scratch (static device globals; no allocations) ----------
__device__ float g_xn  [T_ * H_];      // rmsnorm2 exact (router input)
__device__ float g_xnr [T_ * H_];      // rmsnorm tf32-rounded (GEMM A)
__device__ float g_q   [T_ * H_];
__device__ float g_k   [T_ * H_];
__device__ float g_v   [T_ * H_];
__device__ float g_ctx [T_ * H_];      // tf32-rounded at flash epilogue
__device__ float g_h1  [T_ * H_];      // residual after attention
__device__ float g_a1  [2 * T_ * I_];  // up-proj (w1) -> silu*gate, tf32-rounded
__device__ float g_a3  [2 * T_ * I_];
__device__ int   g_cnt [E_];
__device__ int   g_tok [E_ * T_];
__device__ int   g_aid [E_ * T_];
__device__ float g_coef[E_ * T_];
// tf32-rounded weight copies
__device__ float g_wq[H_ * H_], g_wk[H_ * H_], g_wv[H_ * H_], g_wo[H_ * H_];
__device__ float g_w1[E_ * H_ * I_], g_w2[E_ * I_ * H_], g_w3[E_ * H_ * I_];

// ---------------- tf32 round-to-nearest helper -----------------------------
__device__ __forceinline__ float tf32r(float x)
{
    unsigned r;
    asm("cvt.rna.tf32.f32 %0, %1;" : "=r"(r) : "f"(x));
    return __uint_as_float(r);
}

__global__ void tf32_round_kernel(const float4* __restrict__ s, float4* __restrict__ d, int n4)
{
    int i = blockIdx.x * blockDim.x + threadIdx.x;
    if (i >= n4) return;
    float4 v = s[i];
    v.x = tf32r(v.x); v.y = tf32r(v.y); v.z = tf32r(v.z); v.w = tf32r(v.w);
    d[i] = v;
}

// ---------------- rmsnorm: rounded out (+ optional exact out + residual copy)
__global__ void rmsnorm_kernel(const float* __restrict__ x, const float* __restrict__ w,
                               float* __restrict__ outr, float* __restrict__ oute,
                               float* __restrict__ cpy)
{
    const int t   = blockIdx.x;
    const int tid = threadIdx.x;                  // 256 threads, 8 elems each
    const float* xr = x + (size_t)t * H_;
    float4 v0 = *(const float4*)(xr + tid * 4);
    float4 v1 = *(const float4*)(xr + 1024 + tid * 4);
    float ss = v0.x*v0.x + v0.y*v0.y + v0.z*v0.z + v0.w*v0.w
             + v1.x*v1.x + v1.y*v1.y + v1.z*v1.z + v1.w*v1.w;
#pragma unroll
    for (int o = 16; o > 0; o >>= 1) ss += __shfl_down_sync(0xffffffffu, ss, o);
    __shared__ float wsum[8];
    __shared__ float rsh;
    if ((tid & 31) == 0) wsum[tid >> 5] = ss;
    __syncthreads();
    if (tid == 0) {
        float tot = 0.f;
#pragma unroll
        for (int i = 0; i < 8; i++) tot += wsum[i];
        rsh = rsqrtf(tot * (1.f / H_) + EPS_);
    }
    __syncthreads();
    const float r = rsh;
    float4 w0 = *(const float4*)(w + tid * 4);
    float4 w1 = *(const float4*)(w + 1024 + tid * 4);
    float4 o0 = make_float4(v0.x*r*w0.x, v0.y*r*w0.y, v0.z*r*w0.z, v0.w*r*w0.w);
    float4 o1 = make_float4(v1.x*r*w1.x, v1.y*r*w1.y, v1.z*r*w1.z, v1.w*r*w1.w);
    if (oute) {
        float* ep = oute + (size_t)t * H_;
        *(float4*)(ep + tid * 4)        = o0;
        *(float4*)(ep + 1024 + tid * 4) = o1;
    }
    float4 r0 = make_float4(tf32r(o0.x), tf32r(o0.y), tf32r(o0.z), tf32r(o0.w));
    float4 r1 = make_float4(tf32r(o1.x), tf32r(o1.y), tf32r(o1.z), tf32r(o1.w));
    float* op = outr + (size_t)t * H_;
    *(float4*)(op + tid * 4)        = r0;
    *(float4*)(op + 1024 + tid * 4) = r1;
    if (cpy) {
        float* cp = cpy + (size_t)t * H_;
        *(float4*)(cp + tid * 4)        = v0;
        *(float4*)(cp + 1024 + tid * 4) = v1;
    }
}

// ======================= tf32 tensor-core GEMM ==============================
// C[M,N] = A[M,K] @ B[K,N]. CTA tile 128x128, BK=32, 256 threads (8 warps
// as 2x4, warp tile 64x32). cp.async double-buffered SMEM. A fragments via
// ldmatrix.x4, B fragments via scalar LDS (B stays [K][N] -> coalesced gmem).
// mode 0: dense (optional addend).  arow/crow null, cnt=M.
// mode 1: gather A rows by arow, store C rows to crow.
// mode 2: gather A rows by arow, atomicAdd cscale[row]*C into crow rows.
#define BK_  32
#define AST_ 36                 // A smem row stride (pad -> conflict-free LDSM)
#define BST_ 132                // B smem row stride
#define ASZ_ (128 * AST_)       // 4608 floats per stage
#define BSZ_ (BK_ * BST_)       // 4224 floats per stage
#define MMA_SMEM ((2 * ASZ_ + 2 * BSZ_) * 4)   // 70656 B

__device__ __forceinline__ unsigned smem_u32(const void* p)
{
    return (unsigned)__cvta_generic_to_shared(p);
}
__device__ __forceinline__ void cp16(void* dst, const void* src, int bytes)
{
    asm volatile("cp.async.cg.shared.global [%0], [%1], 16, %2;\n"
                 :: "r"(smem_u32(dst)), "l"(src), "r"(bytes));
}

__global__ __launch_bounds__(256) void mma_gemm(
    const float* __restrict__ A, const float* __restrict__ Bb,
    float* __restrict__ C, const float* __restrict__ addend,
    const int* __restrict__ counts, const int* __restrict__ arow_l,
    const int* __restrict__ crow_l, const float* __restrict__ cscale_l,
    int M, int N, int K, int mode)
{
    const int e   = blockIdx.z;
    const int cnt = counts ? counts[e] : M;
    const int m0  = blockIdx.y * 128;
    if (m0 >= cnt) return;
    const int n0  = blockIdx.x * 128;
    const float* B  = Bb + (size_t)e * K * N;
    const int*   ar = arow_l   ? arow_l   + e * T_ : nullptr;
    const int*   cr = crow_l   ? crow_l   + e * T_ : nullptr;
    const float* cs = cscale_l ? cscale_l + e * T_ : nullptr;

    extern __shared__ float sm[];
    float* As = sm;
    float* Bs = sm + 2 * ASZ_;

    const int tid = threadIdx.x, lane = tid & 31, warp = tid >> 5;
    const int wm = (warp >> 2) * 64, wn = (warp & 3) * 32;

    // A copy: 1024 float4 / stage; id -> row=id>>3, col4=(id&7)*4
    const float* aptr[4];
    int abytes[4];
#pragma unroll
    for (int i = 0; i < 4; i++) {
        const int id  = tid + 256 * i;
        const int row = id >> 3, c4 = (id & 7) << 2;
        const int r   = m0 + row;
        const bool ok = (r < cnt);
        const int grow = ok ? (ar ? ar[r] : r) : 0;
        aptr[i]   = A + (size_t)grow * K + c4;
        abytes[i] = ok ? 16 : 0;
    }

    auto do_copy = [&](int st, int k0) {
        float* as = As + st * ASZ_;
        float* bs = Bs + st * BSZ_;
#pragma unroll
        for (int i = 0; i < 4; i++) {
            const int id  = tid + 256 * i;
            const int row = id >> 3, c4 = (id & 7) << 2;
            cp16(&as[row * AST_ + c4], aptr[i] + k0, abytes[i]);
        }
#pragma unroll
        for (int i = 0; i < 4; i++) {
            const int id = tid + 256 * i;
            const int kr = id >> 5, c4 = (id & 31) << 2;
            cp16(&bs[kr * BST_ + c4], B + (size_t)(k0 + kr) * N + n0 + c4, 16);
        }
    };

    float acc[4][4][4];
#pragma unroll
    for (int i = 0; i < 4; i++)
#pragma unroll
        for (int j = 0; j < 4; j++)
#pragma unroll
            for (int c = 0; c < 4; c++) acc[i][j][c] = 0.f;

    do_copy(0, 0);
    asm volatile("cp.async.commit_group;\n");

    const int NIT = K / BK_;
    for (int it = 0; it < NIT; ++it) {
        if (it + 1 < NIT) do_copy((it + 1) & 1, (it + 1) * BK_);
        asm volatile("cp.async.commit_group;\n");
        asm volatile("cp.async.wait_group 1;\n");
        __syncthreads();
        const float* as = As + (it & 1) * ASZ_;
        const float* bs = Bs + (it & 1) * BSZ_;
#pragma unroll
        for (int ks = 0; ks < 4; ks++) {
            const int c0 = ks * 8;
            unsigned af[4][4];
#pragma unroll
            for (int i = 0; i < 4; i++) {
                const int row = wm + 16 * i + (lane & 7) + ((lane >> 3) & 1) * 8;
                const int col = c0 + (lane >> 4) * 4;
                const unsigned addr = smem_u32(&as[row * AST_ + col]);
                asm volatile("ldmatrix.sync.aligned.m8n8.x4.shared.b16 {%0,%1,%2,%3}, [%4];\n"
                             : "=r"(af[i][0]), "=r"(af[i][1]), "=r"(af[i][2]), "=r"(af[i][3])
                             : "r"(addr));
            }
            unsigned bf[4][2];
            const int kk = lane & 3, nn = lane >> 2;
#pragma unroll
            for (int j = 0; j < 4; j++) {
                bf[j][0] = __float_as_uint(bs[(c0 + kk) * BST_ + wn + 8 * j + nn]);
                bf[j][1] = __float_as_uint(bs[(c0 + 4 + kk) * BST_ + wn + 8 * j + nn]);
            }
#pragma unroll
            for (int i = 0; i < 4; i++)
#pragma unroll
                for (int j = 0; j < 4; j++) {
                    asm volatile(
                        "mma.sync.aligned.m16n8k8.row.col.f32.tf32.tf32.f32 "
                        "{%0,%1,%2,%3}, {%4,%5,%6,%7}, {%8,%9}, {%0,%1,%2,%3};\n"
                        : "+f"(acc[i][j][0]), "+f"(acc[i][j][1]),
                          "+f"(acc[i][j][2]), "+f"(acc[i][j][3])
                        : "r"(af[i][0]), "r"(af[i][1]), "r"(af[i][2]), "r"(af[i][3]),
                          "r"(bf[j][0]), "r"(bf[j][1]));
                }
        }
        __syncthreads();
    }

    // ---------------- epilogue ----------------
#pragma unroll
    for (int i = 0; i < 4; i++) {
        const int lr0 = wm + 16 * i + (lane >> 2);
        const int gr0 = m0 + lr0, gr1 = gr0 + 8;
        const bool ok0 = gr0 < cnt, ok1 = gr1 < cnt;
        if (mode == 2) {
            const float s0 = ok0 ? cs[gr0] : 0.f;
            const float s1 = ok1 ? cs[gr1] : 0.f;
            const int   o0 = ok0 ? cr[gr0] : 0;
            const int   o1 = ok1 ? cr[gr1] : 0;
#pragma unroll
            for (int j = 0; j < 4; j++) {
                const int c = n0 + wn + 8 * j + 2 * (lane & 3);
                if (ok0) {
                    atomicAdd(&C[(size_t)o0 * N + c],     s0 * acc[i][j][0]);
                    atomicAdd(&C[(size_t)o0 * N + c + 1], s0 * acc[i][j][1]);
                }
                if (ok1) {
                    atomicAdd(&C[(size_t)o1 * N + c],     s1 * acc[i][j][2]);
                    atomicAdd(&C[(size_t)o1 * N + c + 1], s1 * acc[i][j][3]);
                }
            }
        } else if (mode == 1) {
            const int o0 = ok0 ? cr[gr0] : 0;
            const int o1 = ok1 ? cr[gr1] : 0;
#pragma unroll
            for (int j = 0; j < 4; j++) {
                const int c = n0 + wn + 8 * j + 2 * (lane & 3);
                if (ok0) *(float2*)&C[(size_t)o0 * N + c] = make_float2(acc[i][j][0], acc[i][j][1]);
                if (ok1) *(float2*)&C[(size_t)o1 * N + c] = make_float2(acc[i][j][2], acc[i][j][3]);
            }
        } else {
#pragma unroll
            for (int j = 0; j < 4; j++) {
                const int c = n0 + wn + 8 * j + 2 * (lane & 3);
                float2 v0 = make_float2(acc[i][j][0], acc[i][j][1]);
                float2 v1 = make_float2(acc[i][j][2], acc[i][j][3]);
                if (addend) {
                    float2 a0 = *(const float2*)&addend[(size_t)gr0 * N + c];
                    float2 a1 = *(const float2*)&addend[(size_t)gr1 * N + c];
                    v0.x += a0.x; v0.y += a0.y; v1.x += a1.x; v1.y += a1.y;
                }
                *(float2*)&C[(size_t)gr0 * N + c] = v0;
                *(float2*)&C[(size_t)gr1 * N + c] = v1;
            }
        }
    }
}

// ---------------- RoPE (in-place on q and k) -------------------------------
__global__ void rope_kernel(float* __restrict__ q, float* __restrict__ k,
                            const int* __restrict__ pos_ids)
{
    const int idx = blockIdx.x * blockDim.x + threadIdx.x;   // T*NH*64
    if (idx >= T_ * NH_ * 64) return;
    const int d  = idx & 63;
    const int hh = (idx >> 6) & (NH_ - 1);
    const int t  = idx >> 10;
    const float pos = (float)pos_ids[t];
    const float inv = expf(-0.14391156831212787f * (float)d);
    float sv, cv;
    sincosf(pos * inv, &sv, &cv);
    const size_t base = (size_t)t * H_ + hh * HD_ + d;
    float q1 = q[base], q2 = q[base + 64];
    q[base]      = q1 * cv - q2 * sv;
    q[base + 64] = q2 * cv + q1 * sv;
    float k1 = k[base], k2 = k[base + 64];
    k[base]      = k1 * cv - k2 * sv;
    k[base + 64] = k2 * cv + k1 * sv;
}

// ---------------- causal flash attention (fp32, Br=Bc=64, 512 threads) -----
#define FLASH_SMEM ((64*128 + 64*132 + 64*128 + 64*68) * 4)

__global__ void flash_kernel(const float* __restrict__ q, const float* __restrict__ k,
                             const float* __restrict__ v, float* __restrict__ ctx)
{
    extern __shared__ float sm[];
    float* Qs = sm;                     // [64][128]
    float* Ks = Qs + 64 * 128;          // [64][132]
    float* Vs = Ks + 64 * 132;          // [64][128]
    float* Ss = Vs + 64 * 128;          // [64][68]

    const int qt = blockIdx.x, hh = blockIdx.y, b = blockIdx.z;
    const int tid = threadIdx.x;        // 512

    const size_t qbase = ((size_t)(b * S_ + qt * 64)) * H_ + hh * HD_;
#pragma unroll
    for (int g = 0; g < 4; g++) {
        const int gid = g * 512 + tid;
        const int r = gid >> 5, c4 = (gid & 31) << 2;
        *(float4*)&Qs[r * 128 + c4] = *(const float4*)(q + qbase + (size_t)r * H_ + c4);
    }

    const int row = tid >> 3, part = tid & 7;
    const int sy  = tid >> 4, sx  = tid & 15;
    float m_i = -FLT_MAX, l_i = 0.f;
    float acc[16];
#pragma unroll
    for (int c = 0; c < 16; c++) acc[c] = 0.f;

    for (int kc = 0; kc <= qt; kc++) {
        __syncthreads();
        const size_t kbase = ((size_t)(b * S_ + kc * 64)) * H_ + hh * HD_;
#pragma unroll
        for (int g = 0; g < 4; g++) {
            const int gid = g * 512 + tid;
            const int r = gid >> 5, c4 = (gid & 31) << 2;
            *(float4*)&Ks[r * 132 + c4] = *(const float4*)(k + kbase + (size_t)r * H_ + c4);
            *(float4*)&Vs[r * 128 + c4] = *(const float4*)(v + kbase + (size_t)r * H_ + c4);
        }
        __syncthreads();

        float cc[2][4];
#pragma unroll
        for (int i = 0; i < 2; i++)
#pragma unroll
            for (int j = 0; j < 4; j++) cc[i][j] = 0.f;
        const float* qp0 = &Qs[(2 * sy) * 128];
        const float* qp1 = qp0 + 128;
#pragma unroll 8
        for (int k4 = 0; k4 < 32; k4++) {
            float4 a0 = *(const float4*)(qp0 + 4 * k4);
            float4 a1 = *(const float4*)(qp1 + 4 * k4);
#pragma unroll
            for (int j = 0; j < 4; j++) {
                float4 bb = *(const float4*)&Ks[(4 * sx + j) * 132 + 4 * k4];
                cc[0][j] += a0.x*bb.x + a0.y*bb.y + a0.z*bb.z + a0.w*bb.w;
                cc[1][j] += a1.x*bb.x + a1.y*bb.y + a1.z*bb.z + a1.w*bb.w;
            }
        }
        const bool diag = (kc == qt);
#pragma unroll
        for (int i = 0; i < 2; i++)
#pragma unroll
            for (int j = 0; j < 4; j++) {
                const int rr = 2 * sy + i, cl = 4 * sx + j;
                float val = cc[i][j] * SCALE_;
                if (diag && cl > rr) val = -1e30f;
                Ss[rr * 68 + cl] = val;
            }
        __syncthreads();

        const float* srow = &Ss[row * 68];
        float mx = m_i;
#pragma unroll 16
        for (int j = 0; j < 64; j++) mx = fmaxf(mx, srow[j]);
        const float alpha = __expf(m_i - mx);
        m_i = mx;
        l_i *= alpha;
#pragma unroll
        for (int c = 0; c < 16; c++) acc[c] *= alpha;
        const float* vp = &Vs[part * 16];
#pragma unroll 4
        for (int j = 0; j < 64; j++) {
            const float p = __expf(srow[j] - mx);
            l_i += p;
            const float* vj = vp + j * 128;
            float4 v0 = *(const float4*)(vj);
            float4 v1 = *(const float4*)(vj + 4);
            float4 v2 = *(const float4*)(vj + 8);
            float4 v3 = *(const float4*)(vj + 12);
            acc[ 0] += p * v0.x; acc[ 1] += p * v0.y; acc[ 2] += p * v0.z; acc[ 3] += p * v0.w;
            acc[ 4] += p * v1.x; acc[ 5] += p * v1.y; acc[ 6] += p * v1.z; acc[ 7] += p * v1.w;
            acc[ 8] += p * v2.x; acc[ 9] += p * v2.y; acc[10] += p * v2.z; acc[11] += p * v2.w;
            acc[12] += p * v3.x; acc[13] += p * v3.y; acc[14] += p * v3.z; acc[15] += p * v3.w;
        }
    }

    const float invl = 1.f / l_i;
    float* op = ctx + ((size_t)(b * S_ + qt * 64 + row)) * H_ + hh * HD_ + part * 16;
    *(float4*)(op + 0)  = make_float4(tf32r(acc[0]*invl),  tf32r(acc[1]*invl),
                                      tf32r(acc[2]*invl),  tf32r(acc[3]*invl));
    *(float4*)(op + 4)  = make_float4(tf32r(acc[4]*invl),  tf32r(acc[5]*invl),
                                      tf32r(acc[6]*invl),  tf32r(acc[7]*invl));
    *(float4*)(op + 8)  = make_float4(tf32r(acc[8]*invl),  tf32r(acc[9]*invl),
                                      tf32r(acc[10]*invl), tf32r(acc[11]*invl));
    *(float4*)(op + 12) = make_float4(tf32r(acc[12]*invl), tf32r(acc[13]*invl),
                                      tf32r(acc[14]*invl), tf32r(acc[15]*invl));
}

// ---------------- router ---------------------------------------------------
__global__ void zero_counts_kernel(int* c)
{
    if (threadIdx.x < E_) c[threadIdx.x] = 0;
}

__global__ void router_kernel(const float* __restrict__ xn, const float* __restrict__ rw,
                              int* __restrict__ counts, int* __restrict__ tok,
                              int* __restrict__ aid, float* __restrict__ coef)
{
    const int t = blockIdx.x;
    const int tid = threadIdx.x;     // 256
    float a[8] = {0.f,0.f,0.f,0.f,0.f,0.f,0.f,0.f};
    const float* xr = xn + (size_t)t * H_;
    for (int kk = tid; kk < H_; kk += 256) {
        const float xv = xr[kk];
        float4 r0 = *(const float4*)(rw + kk * 8);
        float4 r1 = *(const float4*)(rw + kk * 8 + 4);
        a[0] += xv * r0.x; a[1] += xv * r0.y; a[2] += xv * r0.z; a[3] += xv * r0.w;
        a[4] += xv * r1.x; a[5] += xv * r1.y; a[6] += xv * r1.z; a[7] += xv * r1.w;
    }
#pragma unroll
    for (int o = 16; o > 0; o >>= 1)
#pragma unroll
        for (int e = 0; e < 8; e++) a[e] += __shfl_down_sync(0xffffffffu, a[e], o);
    __shared__ float ws[8][8];
    if ((tid & 31) == 0)
#pragma unroll
        for (int e = 0; e < 8; e++) ws[tid >> 5][e] = a[e];
    __syncthreads();
    if (tid == 0) {
        float lg[8];
#pragma unroll
        for (int e = 0; e < 8; e++) {
            float s = 0.f;
#pragma unroll
            for (int w = 0; w < 8; w++) s += ws[w][e];
            lg[e] = s;
        }
        int i1 = 0;
#pragma unroll
        for (int e = 1; e < 8; e++) if (lg[e] > lg[i1]) i1 = e;
        int i2 = (i1 == 0) ? 1 : 0;
#pragma unroll
        for (int e = 0; e < 8; e++) if (e != i1 && lg[e] > lg[i2]) i2 = e;
        const float ex = expf(lg[i2] - lg[i1]);
        const float c1 = 1.f / (1.f + ex);
        const float c2 = ex / (1.f + ex);
        int s1 = atomicAdd(&counts[i1], 1);
        tok[i1 * T_ + s1] = t; aid[i1 * T_ + s1] = 2 * t;     coef[i1 * T_ + s1] = c1;
        int s2 = atomicAdd(&counts[i2], 1);
        tok[i2 * T_ + s2] = t; aid[i2 * T_ + s2] = 2 * t + 1; coef[i2 * T_ + s2] = c2;
    }
}

// ---------------- fused SiLU * gate (tf32-rounded output) ------------------
__global__ void silu_mul_kernel(float4* __restrict__ a1, const float4* __restrict__ a3, int n4)
{
    const int i = blockIdx.x * blockDim.x + threadIdx.x;
    if (i >= n4) return;
    float4 g = a1[i];
    float4 u = a3[i];
    g.x = tf32r((g.x / (1.f + __expf(-g.x))) * u.x);
    g.y = tf32r((g.y / (1.f + __expf(-g.y))) * u.y);
    g.z = tf32r((g.z / (1.f + __expf(-g.z))) * u.z);
    g.w = tf32r((g.w / (1.f + __expf(-g.w))) * u.w);
    a1[i] = g;
}

// ---------------- launcher -------------------------------------------------
extern "C" void kernel_launch(void* const* d_in, const int* in_sizes, int n_in,
                              void* d_out, int out_size)
{
    const float* hidden   = (const float*)d_in[0];
    const int*   pos      = (const int*)  d_in[1];
    const float* rms1_w   = (const float*)d_in[2];
    const float* rms2_w   = (const float*)d_in[3];
    const float* q_w      = (const float*)d_in[4];
    const float* k_w      = (const float*)d_in[5];
    const float* v_w      = (const float*)d_in[6];
    const float* o_w      = (const float*)d_in[7];
    const float* router_w = (const float*)d_in[8];
    const float* w1       = (const float*)d_in[9];
    const float* w2       = (const float*)d_in[10];
    const float* w3       = (const float*)d_in[11];
    float* out = (float*)d_out;

    float *xn, *xnr, *qb, *kb, *vb, *ctx, *h1, *a1, *a3, *coef;
    float *wq, *wk, *wv, *wo, *w1r, *w2r, *w3r;
    int *cnt, *tokl, *aidl;
    cudaGetSymbolAddress((void**)&xn,   g_xn);
    cudaGetSymbolAddress((void**)&xnr,  g_xnr);
    cudaGetSymbolAddress((void**)&qb,   g_q);
    cudaGetSymbolAddress((void**)&kb,   g_k);
    cudaGetSymbolAddress((void**)&vb,   g_v);
    cudaGetSymbolAddress((void**)&ctx,  g_ctx);
    cudaGetSymbolAddress((void**)&h1,   g_h1);
    cudaGetSymbolAddress((void**)&a1,   g_a1);
    cudaGetSymbolAddress((void**)&a3,   g_a3);
    cudaGetSymbolAddress((void**)&coef, g_coef);
    cudaGetSymbolAddress((void**)&cnt,  g_cnt);
    cudaGetSymbolAddress((void**)&tokl, g_tok);
    cudaGetSymbolAddress((void**)&aidl, g_aid);
    cudaGetSymbolAddress((void**)&wq,   g_wq);
    cudaGetSymbolAddress((void**)&wk,   g_wk);
    cudaGetSymbolAddress((void**)&wv,   g_wv);
    cudaGetSymbolAddress((void**)&wo,   g_wo);
    cudaGetSymbolAddress((void**)&w1r,  g_w1);
    cudaGetSymbolAddress((void**)&w2r,  g_w2);
    cudaGetSymbolAddress((void**)&w3r,  g_w3);

    cudaFuncSetAttribute(mma_gemm, cudaFuncAttributeMaxDynamicSharedMemorySize, MMA_SMEM);
    cudaFuncSetAttribute(flash_kernel, cudaFuncAttributeMaxDynamicSharedMemorySize, FLASH_SMEM);

    auto roundw = [](const float* s, float* d, size_t n) {
        int n4 = (int)(n / 4);
        tf32_round_kernel<<<(n4 + 255) / 256, 256>>>((const float4*)s, (float4*)d, n4);
    };
    // 0. round all weights to tf32 (rna)
    roundw(q_w, wq, (size_t)H_ * H_);
    roundw(k_w, wk, (size_t)H_ * H_);
    roundw(v_w, wv, (size_t)H_ * H_);
    roundw(o_w, wo, (size_t)H_ * H_);
    roundw(w1,  w1r, (size_t)E_ * H_ * I_);
    roundw(w2,  w2r, (size_t)E_ * I_ * H_);
    roundw(w3,  w3r, (size_t)E_ * H_ * I_);

    const dim3 dg(H_ / 128, T_ / 128, 1);
    const dim3 eg(H_ / 128, T_ / 128, E_);

    // 1. pre-attention rmsnorm (rounded only)
    rmsnorm_kernel<<<T_, 256>>>(hidden, rms1_w, xnr, nullptr, nullptr);
    // 2. Q/K/V projections (tensor cores)
    mma_gemm<<<dg, 256, MMA_SMEM>>>(xnr, wq, qb, nullptr, nullptr, nullptr, nullptr, nullptr,
                                    T_, H_, H_, 0);
    mma_gemm<<<dg, 256, MMA_SMEM>>>(xnr, wk, kb, nullptr, nullptr, nullptr, nullptr, nullptr,
                                    T_, H_, H_, 0);
    mma_gemm<<<dg, 256, MMA_SMEM>>>(xnr, wv, vb, nullptr, nullptr, nullptr, nullptr, nullptr,
                                    T_, H_, H_, 0);
    // 3. RoPE in place
    rope_kernel<<<(T_ * NH_ * 64) / 256, 256>>>(qb, kb, pos);
    // 4. causal flash attention (writes tf32-rounded ctx)
    flash_kernel<<<dim3(S_ / 64, NH_, 2), 512, FLASH_SMEM>>>(qb, kb, vb, ctx);
    // 5. O projection + residual
    mma_gemm<<<dg, 256, MMA_SMEM>>>(ctx, wo, h1, hidden, nullptr, nullptr, nullptr, nullptr,
                                    T_, H_, H_, 0);
    // 6. post-attention rmsnorm: rounded (GEMM A) + exact (router) + seed out with h1
    rmsnorm_kernel<<<T_, 256>>>(h1, rms2_w, xnr, xn, out);
    // 7. routing (exact activations)
    zero_counts_kernel<<<1, 32>>>(cnt);
    router_kernel<<<T_, 256>>>(xn, router_w, cnt, tokl, aidl, coef);
    // 8. expert up-projections (gathered rows, tensor cores)
    mma_gemm<<<eg, 256, MMA_SMEM>>>(xnr, w1r, a1, nullptr, cnt, tokl, aidl, nullptr,
                                    T_, I_, H_, 1);
    mma_gemm<<<eg, 256, MMA_SMEM>>>(xnr, w3r, a3, nullptr, cnt, tokl, aidl, nullptr,
                                    T_, I_, H_, 1);
    // 9. fused activation (tf32-rounded)
    silu_mul_kernel<<<(2 * T_ * I_ / 4 + 255) / 256, 256>>>((float4*)a1, (const float4*)a3,
                                                            2 * T_ * I_ / 4);
    // 10. down projection: atomic scatter coeff * result into out (= h1 + moe)
    mma_gemm<<<eg, 256, MMA_SMEM>>>(a1, w2r, out, nullptr, cnt, aidl, tokl, coef,
                                    T_, H_, I_, 2);
}

// round 10
// speedup vs baseline: 1.8936x; 1.0637x over previous
#include <cuda_runtime.h>
#include <math.h>
#include <float.h>
#include <stdint.h>

// Problem constants
#define T_   4096      // B*S tokens
#define H_   2048
#define S_   2048
#define NH_  16
#define HD_  128
#define E_   8
#define I_   2048
#define EPS_ 1e-5f
#define SCALE_ 0.08838834764831845f  // 1/sqrt(128)

// ---------------- scratch (static device globals; no allocations) ----------
__device__ float g_xn  [T_ * H_];      // rmsnorm2 exact (router input)
__device__ float g_xnr [T_ * H_];      // rmsnorm tf32-rounded (GEMM A)
__device__ float g_q   [T_ * H_];
__device__ float g_k   [T_ * H_];
__device__ float g_v   [T_ * H_];
__device__ float g_ctx [T_ * H_];
__device__ float g_h1  [T_ * H_];
__device__ float g_a1  [2 * T_ * I_];
__device__ float g_a3  [2 * T_ * I_];
__device__ int   g_cnt [E_];
__device__ int   g_tok [E_ * T_];
__device__ int   g_aid [E_ * T_];
__device__ float g_coef[E_ * T_];
// transposed + tf32-rounded weights ([N][K] K-major)
__device__ float g_wqT[H_ * H_], g_wkT[H_ * H_], g_wvT[H_ * H_], g_woT[H_ * H_];
__device__ float g_w1T[E_ * H_ * I_], g_w2T[E_ * I_ * H_], g_w3T[E_ * H_ * I_];

// ---------------- helpers --------------------------------------------------
__device__ __forceinline__ float tf32r(float x)
{
    unsigned r;
    asm("cvt.rna.tf32.f32 %0, %1;" : "=r"(r) : "f"(x));
    return __uint_as_float(r);
}
__device__ __forceinline__ unsigned smem_u32(const void* p)
{
    return (unsigned)__cvta_generic_to_shared(p);
}
__device__ __forceinline__ void cp16(uint32_t daddr, const void* src, int bytes)
{
    asm volatile("cp.async.cg.shared.global [%0], [%1], 16, %2;\n"
                 :: "r"(daddr), "l"(src), "r"(bytes));
}

// ---------------- weight transpose + tf32 round (2048x2048 mats) -----------
__global__ void wtrans_kernel(const float* __restrict__ S, float* __restrict__ D)
{
    __shared__ float t[32][33];
    const size_t mo = (size_t)blockIdx.z * H_ * H_;
    const float* s = S + mo;
    float* d = D + mo;
    const int x0 = blockIdx.x * 32, y0 = blockIdx.y * 32;
    const int tx = threadIdx.x, ty = threadIdx.y;   // 32 x 8
#pragma unroll
    for (int j = 0; j < 4; j++)
        t[ty + 8 * j][tx] = s[(size_t)(y0 + ty + 8 * j) * H_ + x0 + tx];
    __syncthreads();
#pragma unroll
    for (int j = 0; j < 4; j++)
        d[(size_t)(x0 + ty + 8 * j) * H_ + y0 + tx] = tf32r(t[tx][ty + 8 * j]);
}

// ---------------- rmsnorm: rounded out (+ optional exact out + copy) -------
__global__ void rmsnorm_kernel(const float* __restrict__ x, const float* __restrict__ w,
                               float* __restrict__ outr, float* __restrict__ oute,
                               float* __restrict__ cpy)
{
    const int t   = blockIdx.x;
    const int tid = threadIdx.x;
    const float* xr = x + (size_t)t * H_;
    float4 v0 = *(const float4*)(xr + tid * 4);
    float4 v1 = *(const float4*)(xr + 1024 + tid * 4);
    float ss = v0.x*v0.x + v0.y*v0.y + v0.z*v0.z + v0.w*v0.w
             + v1.x*v1.x + v1.y*v1.y + v1.z*v1.z + v1.w*v1.w;
#pragma unroll
    for (int o = 16; o > 0; o >>= 1) ss += __shfl_down_sync(0xffffffffu, ss, o);
    __shared__ float wsum[8];
    __shared__ float rsh;
    if ((tid & 31) == 0) wsum[tid >> 5] = ss;
    __syncthreads();
    if (tid == 0) {
        float tot = 0.f;
#pragma unroll
        for (int i = 0; i < 8; i++) tot += wsum[i];
        rsh = rsqrtf(tot * (1.f / H_) + EPS_);
    }
    __syncthreads();
    const float r = rsh;
    float4 w0 = *(const float4*)(w + tid * 4);
    float4 w1 = *(const float4*)(w + 1024 + tid * 4);
    float4 o0 = make_float4(v0.x*r*w0.x, v0.y*r*w0.y, v0.z*r*w0.z, v0.w*r*w0.w);
    float4 o1 = make_float4(v1.x*r*w1.x, v1.y*r*w1.y, v1.z*r*w1.z, v1.w*r*w1.w);
    if (oute) {
        float* ep = oute + (size_t)t * H_;
        *(float4*)(ep + tid * 4)        = o0;
        *(float4*)(ep + 1024 + tid * 4) = o1;
    }
    float4 r0 = make_float4(tf32r(o0.x), tf32r(o0.y), tf32r(o0.z), tf32r(o0.w));
    float4 r1 = make_float4(tf32r(o1.x), tf32r(o1.y), tf32r(o1.z), tf32r(o1.w));
    float* op = outr + (size_t)t * H_;
    *(float4*)(op + tid * 4)        = r0;
    *(float4*)(op + 1024 + tid * 4) = r1;
    if (cpy) {
        float* cp = cpy + (size_t)t * H_;
        *(float4*)(cp + tid * 4)        = v0;
        *(float4*)(cp + 1024 + tid * 4) = v1;
    }
}

// ================= tf32 mma.sync GEMM (ldmatrix A and B) ====================
// C[M,N] = A[M,K] @ BT[N,K]^T.  CTA tile 128x128, BK=32, 256 threads
// (8 warps as 2Mx4N, warp tile 64x32). Both A and BT tiles in XOR-swizzled
// stride-32 smem (conflict-free ldmatrix). cp.async 2-stage pipeline.
// mode 0: dense (+opt addend); 1: gather A rows, store C to crow;
// mode 2: gather A rows, atomicAdd cscale*acc into crow rows.
#define BK_   32
#define STG_  16384                     // 128 rows * 32 floats * 4B per tile
#define SA0_  0
#define SB0_  16384
#define SA1_  32768
#define SB1_  49152
#define MMA_SMEM 65536
// swizzled byte offset for (row, 16B-chunk ch)
#define SWOFF(row, ch) ((unsigned)(row) * 128u + (unsigned)(((ch) ^ ((row) & 7)) << 4))

__global__ __launch_bounds__(256, 2) void mma_gemm(
    const float* __restrict__ A, const float* __restrict__ BT,
    float* __restrict__ C, const float* __restrict__ addend,
    const int* __restrict__ counts, const int* __restrict__ arow_l,
    const int* __restrict__ crow_l, const float* __restrict__ cscale_l,
    int M, int N, int K, int mode)
{
    const int e   = blockIdx.z;
    const int cnt = counts ? counts[e] : M;
    const int m0  = blockIdx.y * 128;
    if (m0 >= cnt) return;
    const int n0  = blockIdx.x * 128;
    const float* Bt = BT + (size_t)e * K * N;
    const int*   ar = arow_l   ? arow_l   + e * T_ : nullptr;
    const int*   cr = crow_l   ? crow_l   + e * T_ : nullptr;
    const float* cs = cscale_l ? cscale_l + e * T_ : nullptr;

    extern __shared__ char smem[];
    const uint32_t sb = smem_u32(smem);
    const int tid = threadIdx.x, lane = tid & 31, warp = tid >> 5;
    const int wm = (warp >> 2) * 64, wn = (warp & 3) * 32;

    // loaders: 4 chunks/thread/tile; row_i = rbase + 32*i, chunk = tid&7
    const int rbase = tid >> 3, ch0 = tid & 7;
    const float* aptr[4];
    int ab[4];
#pragma unroll
    for (int i = 0; i < 4; i++) {
        const int r  = m0 + rbase + 32 * i;
        const bool ok = (r < cnt);
        const int grow = ok ? (ar ? ar[r] : r) : 0;
        aptr[i] = A + (size_t)grow * K + ch0 * 4;
        ab[i]   = ok ? 16 : 0;
    }
    const float* bptr[4];
#pragma unroll
    for (int i = 0; i < 4; i++)
        bptr[i] = Bt + (size_t)(n0 + rbase + 32 * i) * K + ch0 * 4;

    auto load_stage = [&](int st, int k0) {
        const uint32_t abase = sb + (st ? SA1_ : SA0_);
        const uint32_t bbase = sb + (st ? SB1_ : SB0_);
#pragma unroll
        for (int i = 0; i < 4; i++)
            cp16(abase + SWOFF(rbase + 32 * i, ch0), aptr[i] + k0, ab[i]);
#pragma unroll
        for (int i = 0; i < 4; i++)
            cp16(bbase + SWOFF(rbase + 32 * i, ch0), bptr[i] + k0, 16);
        asm volatile("cp.async.commit_group;\n" ::: "memory");
    };

    float acc[4][4][4];
#pragma unroll
    for (int i = 0; i < 4; i++)
#pragma unroll
        for (int j = 0; j < 4; j++)
#pragma unroll
            for (int c = 0; c < 4; c++) acc[i][j][c] = 0.f;

    const int NIT = K / BK_;
    load_stage(0, 0);
    if (NIT > 1) load_stage(1, BK_);

    for (int it = 0; it < NIT; it++) {
        const int st = it & 1;
        if (it + 1 < NIT)
            asm volatile("cp.async.wait_group 1;\n" ::: "memory");
        else
            asm volatile("cp.async.wait_group 0;\n" ::: "memory");
        __syncthreads();
        const uint32_t abase = sb + (st ? SA1_ : SA0_);
        const uint32_t bbase = sb + (st ? SB1_ : SB0_);
#pragma unroll
        for (int ks = 0; ks < 4; ks++) {
            unsigned af[4][4];
#pragma unroll
            for (int i = 0; i < 4; i++) {
                const int row = wm + 16 * i + (lane & 7) + ((lane >> 3) & 1) * 8;
                const int ch  = ks * 2 + (lane >> 4);
                const uint32_t addr = abase + SWOFF(row, ch);
                asm volatile("ldmatrix.sync.aligned.m8n8.x4.shared.b16 {%0,%1,%2,%3}, [%4];\n"
                             : "=r"(af[i][0]), "=r"(af[i][1]), "=r"(af[i][2]), "=r"(af[i][3])
                             : "r"(addr));
            }
            unsigned bfr[4][2];
#pragma unroll
            for (int jj = 0; jj < 4; jj += 2) {
                const int q = lane >> 3;
                const int row = wn + 8 * jj + 8 * (q >> 1) + (lane & 7);
                const int ch  = ks * 2 + (q & 1);
                const uint32_t addr = bbase + SWOFF(row, ch);
                asm volatile("ldmatrix.sync.aligned.m8n8.x4.shared.b16 {%0,%1,%2,%3}, [%4];\n"
                             : "=r"(bfr[jj][0]), "=r"(bfr[jj][1]),
                               "=r"(bfr[jj+1][0]), "=r"(bfr[jj+1][1])
                             : "r"(addr));
            }
#pragma unroll
            for (int i = 0; i < 4; i++)
#pragma unroll
                for (int j = 0; j < 4; j++) {
                    asm volatile(
                        "mma.sync.aligned.m16n8k8.row.col.f32.tf32.tf32.f32 "
                        "{%0,%1,%2,%3}, {%4,%5,%6,%7}, {%8,%9}, {%0,%1,%2,%3};\n"
                        : "+f"(acc[i][j][0]), "+f"(acc[i][j][1]),
                          "+f"(acc[i][j][2]), "+f"(acc[i][j][3])
                        : "r"(af[i][0]), "r"(af[i][1]), "r"(af[i][2]), "r"(af[i][3]),
                          "r"(bfr[j][0]), "r"(bfr[j][1]));
                }
        }
        __syncthreads();
        if (it + 2 < NIT) load_stage(st, (it + 2) * BK_);
    }

    // ---------------- epilogue ----------------
#pragma unroll
    for (int i = 0; i < 4; i++) {
        const int lr0 = wm + 16 * i + (lane >> 2);
        const int gr0 = m0 + lr0, gr1 = gr0 + 8;
        const bool ok0 = gr0 < cnt, ok1 = gr1 < cnt;
        if (mode == 2) {
            const float s0 = ok0 ? cs[gr0] : 0.f;
            const float s1 = ok1 ? cs[gr1] : 0.f;
            const int   o0 = ok0 ? cr[gr0] : 0;
            const int   o1 = ok1 ? cr[gr1] : 0;
#pragma unroll
            for (int j = 0; j < 4; j++) {
                const int c = n0 + wn + 8 * j + 2 * (lane & 3);
                if (ok0) {
                    atomicAdd(&C[(size_t)o0 * N + c],     s0 * acc[i][j][0]);
                    atomicAdd(&C[(size_t)o0 * N + c + 1], s0 * acc[i][j][1]);
                }
                if (ok1) {
                    atomicAdd(&C[(size_t)o1 * N + c],     s1 * acc[i][j][2]);
                    atomicAdd(&C[(size_t)o1 * N + c + 1], s1 * acc[i][j][3]);
                }
            }
        } else if (mode == 1) {
            const int o0 = ok0 ? cr[gr0] : 0;
            const int o1 = ok1 ? cr[gr1] : 0;
#pragma unroll
            for (int j = 0; j < 4; j++) {
                const int c = n0 + wn + 8 * j + 2 * (lane & 3);
                if (ok0) *(float2*)&C[(size_t)o0 * N + c] = make_float2(acc[i][j][0], acc[i][j][1]);
                if (ok1) *(float2*)&C[(size_t)o1 * N + c] = make_float2(acc[i][j][2], acc[i][j][3]);
            }
        } else {
#pragma unroll
            for (int j = 0; j < 4; j++) {
                const int c = n0 + wn + 8 * j + 2 * (lane & 3);
                float2 v0 = make_float2(acc[i][j][0], acc[i][j][1]);
                float2 v1 = make_float2(acc[i][j][2], acc[i][j][3]);
                if (addend) {
                    float2 a0 = *(const float2*)&addend[(size_t)gr0 * N + c];
                    float2 a1 = *(const float2*)&addend[(size_t)gr1 * N + c];
                    v0.x += a0.x; v0.y += a0.y; v1.x += a1.x; v1.y += a1.y;
                }
                *(float2*)&C[(size_t)gr0 * N + c] = v0;
                *(float2*)&C[(size_t)gr1 * N + c] = v1;
            }
        }
    }
}

// ---------------- RoPE (in-place on q and k) -------------------------------
__global__ void rope_kernel(float* __restrict__ q, float* __restrict__ k,
                            const int* __restrict__ pos_ids)
{
    const int idx = blockIdx.x * blockDim.x + threadIdx.x;
    if (idx >= T_ * NH_ * 64) return;
    const int d  = idx & 63;
    const int hh = (idx >> 6) & (NH_ - 1);
    const int t  = idx >> 10;
    const float pos = (float)pos_ids[t];
    const float inv = expf(-0.14391156831212787f * (float)d);
    float sv, cv;
    sincosf(pos * inv, &sv, &cv);
    const size_t base = (size_t)t * H_ + hh * HD_ + d;
    float q1 = q[base], q2 = q[base + 64];
    q[base]      = q1 * cv - q2 * sv;
    q[base + 64] = q2 * cv + q1 * sv;
    float k1 = k[base], k2 = k[base + 64];
    k[base]      = k1 * cv - k2 * sv;
    k[base + 64] = k2 * cv + k1 * sv;
}

// ---------------- causal flash attention (fp32, Br=Bc=64, 512 threads) -----
#define FLASH_SMEM ((64*128 + 64*132 + 64*128 + 64*68) * 4)

__global__ void flash_kernel(const float* __restrict__ q, const float* __restrict__ k,
                             const float* __restrict__ v, float* __restrict__ ctx)
{
    extern __shared__ float sm[];
    float* Qs = sm;
    float* Ks = Qs + 64 * 128;
    float* Vs = Ks + 64 * 132;
    float* Ss = Vs + 64 * 128;

    const int qt = blockIdx.x, hh = blockIdx.y, b = blockIdx.z;
    const int tid = threadIdx.x;

    const size_t qbase = ((size_t)(b * S_ + qt * 64)) * H_ + hh * HD_;
#pragma unroll
    for (int g = 0; g < 4; g++) {
        const int gid = g * 512 + tid;
        const int r = gid >> 5, c4 = (gid & 31) << 2;
        *(float4*)&Qs[r * 128 + c4] = *(const float4*)(q + qbase + (size_t)r * H_ + c4);
    }

    const int row = tid >> 3, part = tid & 7;
    const int sy  = tid >> 4, sx  = tid & 15;
    float m_i = -FLT_MAX, l_i = 0.f;
    float acc[16];
#pragma unroll
    for (int c = 0; c < 16; c++) acc[c] = 0.f;

    for (int kc = 0; kc <= qt; kc++) {
        __syncthreads();
        const size_t kbase = ((size_t)(b * S_ + kc * 64)) * H_ + hh * HD_;
#pragma unroll
        for (int g = 0; g < 4; g++) {
            const int gid = g * 512 + tid;
            const int r = gid >> 5, c4 = (gid & 31) << 2;
            *(float4*)&Ks[r * 132 + c4] = *(const float4*)(k + kbase + (size_t)r * H_ + c4);
            *(float4*)&Vs[r * 128 + c4] = *(const float4*)(v + kbase + (size_t)r * H_ + c4);
        }
        __syncthreads();

        float cc[2][4];
#pragma unroll
        for (int i = 0; i < 2; i++)
#pragma unroll
            for (int j = 0; j < 4; j++) cc[i][j] = 0.f;
        const float* qp0 = &Qs[(2 * sy) * 128];
        const float* qp1 = qp0 + 128;
#pragma unroll 8
        for (int k4 = 0; k4 < 32; k4++) {
            float4 a0 = *(const float4*)(qp0 + 4 * k4);
            float4 a1 = *(const float4*)(qp1 + 4 * k4);
#pragma unroll
            for (int j = 0; j < 4; j++) {
                float4 bb = *(const float4*)&Ks[(4 * sx + j) * 132 + 4 * k4];
                cc[0][j] += a0.x*bb.x + a0.y*bb.y + a0.z*bb.z + a0.w*bb.w;
                cc[1][j] += a1.x*bb.x + a1.y*bb.y + a1.z*bb.z + a1.w*bb.w;
            }
        }
        const bool diag = (kc == qt);
#pragma unroll
        for (int i = 0; i < 2; i++)
#pragma unroll
            for (int j = 0; j < 4; j++) {
                const int rr = 2 * sy + i, cl = 4 * sx + j;
                float val = cc[i][j] * SCALE_;
                if (diag && cl > rr) val = -1e30f;
                Ss[rr * 68 + cl] = val;
            }
        __syncthreads();

        const float* srow = &Ss[row * 68];
        float mx = m_i;
#pragma unroll 16
        for (int j = 0; j < 64; j++) mx = fmaxf(mx, srow[j]);
        const float alpha = __expf(m_i - mx);
        m_i = mx;
        l_i *= alpha;
#pragma unroll
        for (int c = 0; c < 16; c++) acc[c] *= alpha;
        const float* vp = &Vs[part * 16];
#pragma unroll 4
        for (int j = 0; j < 64; j++) {
            const float p = __expf(srow[j] - mx);
            l_i += p;
            const float* vj = vp + j * 128;
            float4 v0 = *(const float4*)(vj);
            float4 v1 = *(const float4*)(vj + 4);
            float4 v2 = *(const float4*)(vj + 8);
            float4 v3 = *(const float4*)(vj + 12);
            acc[ 0] += p * v0.x; acc[ 1] += p * v0.y; acc[ 2] += p * v0.z; acc[ 3] += p * v0.w;
            acc[ 4] += p * v1.x; acc[ 5] += p * v1.y; acc[ 6] += p * v1.z; acc[ 7] += p * v1.w;
            acc[ 8] += p * v2.x; acc[ 9] += p * v2.y; acc[10] += p * v2.z; acc[11] += p * v2.w;
            acc[12] += p * v3.x; acc[13] += p * v3.y; acc[14] += p * v3.z; acc[15] += p * v3.w;
        }
    }

    const float invl = 1.f / l_i;
    float* op = ctx + ((size_t)(b * S_ + qt * 64 + row)) * H_ + hh * HD_ + part * 16;
    *(float4*)(op + 0)  = make_float4(tf32r(acc[0]*invl),  tf32r(acc[1]*invl),
                                      tf32r(acc[2]*invl),  tf32r(acc[3]*invl));
    *(float4*)(op + 4)  = make_float4(tf32r(acc[4]*invl),  tf32r(acc[5]*invl),
                                      tf32r(acc[6]*invl),  tf32r(acc[7]*invl));
    *(float4*)(op + 8)  = make_float4(tf32r(acc[8]*invl),  tf32r(acc[9]*invl),
                                      tf32r(acc[10]*invl), tf32r(acc[11]*invl));
    *(float4*)(op + 12) = make_float4(tf32r(acc[12]*invl), tf32r(acc[13]*invl),
                                      tf32r(acc[14]*invl), tf32r(acc[15]*invl));
}

// ---------------- router ---------------------------------------------------
__global__ void zero_counts_kernel(int* c)
{
    if (threadIdx.x < E_) c[threadIdx.x] = 0;
}

__global__ void router_kernel(const float* __restrict__ xn, const float* __restrict__ rw,
                              int* __restrict__ counts, int* __restrict__ tok,
                              int* __restrict__ aid, float* __restrict__ coef)
{
    const int t = blockIdx.x;
    const int tid = threadIdx.x;
    float a[8] = {0.f,0.f,0.f,0.f,0.f,0.f,0.f,0.f};
    const float* xr = xn + (size_t)t * H_;
    for (int kk = tid; kk < H_; kk += 256) {
        const float xv = xr[kk];
        float4 r0 = *(const float4*)(rw + kk * 8);
        float4 r1 = *(const float4*)(rw + kk * 8 + 4);
        a[0] += xv * r0.x; a[1] += xv * r0.y; a[2] += xv * r0.z; a[3] += xv * r0.w;
        a[4] += xv * r1.x; a[5] += xv * r1.y; a[6] += xv * r1.z; a[7] += xv * r1.w;
    }
#pragma unroll
    for (int o = 16; o > 0; o >>= 1)
#pragma unroll
        for (int e = 0; e < 8; e++) a[e] += __shfl_down_sync(0xffffffffu, a[e], o);
    __shared__ float ws[8][8];
    if ((tid & 31) == 0)
#pragma unroll
        for (int e = 0; e < 8; e++) ws[tid >> 5][e] = a[e];
    __syncthreads();
    if (tid == 0) {
        float lg[8];
#pragma unroll
        for (int e = 0; e < 8; e++) {
            float s = 0.f;
#pragma unroll
            for (int w = 0; w < 8; w++) s += ws[w][e];
            lg[e] = s;
        }
        int i1 = 0;
#pragma unroll
        for (int e = 1; e < 8; e++) if (lg[e] > lg[i1]) i1 = e;
        int i2 = (i1 == 0) ? 1 : 0;
#pragma unroll
        for (int e = 0; e < 8; e++) if (e != i1 && lg[e] > lg[i2]) i2 = e;
        const float ex = expf(lg[i2] - lg[i1]);
        const float c1 = 1.f / (1.f + ex);
        const float c2 = ex / (1.f + ex);
        int s1 = atomicAdd(&counts[i1], 1);
        tok[i1 * T_ + s1] = t; aid[i1 * T_ + s1] = 2 * t;     coef[i1 * T_ + s1] = c1;
        int s2 = atomicAdd(&counts[i2], 1);
        tok[i2 * T_ + s2] = t; aid[i2 * T_ + s2] = 2 * t + 1; coef[i2 * T_ + s2] = c2;
    }
}

// ---------------- fused SiLU * gate (tf32-rounded output) ------------------
__global__ void silu_mul_kernel(float4* __restrict__ a1, const float4* __restrict__ a3, int n4)
{
    const int i = blockIdx.x * blockDim.x + threadIdx.x;
    if (i >= n4) return;
    float4 g = a1[i];
    float4 u = a3[i];
    g.x = tf32r((g.x / (1.f + __expf(-g.x))) * u.x);
    g.y = tf32r((g.y / (1.f + __expf(-g.y))) * u.y);
    g.z = tf32r((g.z / (1.f + __expf(-g.z))) * u.z);
    g.w = tf32r((g.w / (1.f + __expf(-g.w))) * u.w);
    a1[i] = g;
}

// ---------------- launcher -------------------------------------------------
extern "C" void kernel_launch(void* const* d_in, const int* in_sizes, int n_in,
                              void* d_out, int out_size)
{
    const float* hidden   = (const float*)d_in[0];
    const int*   pos      = (const int*)  d_in[1];
    const float* rms1_w   = (const float*)d_in[2];
    const float* rms2_w   = (const float*)d_in[3];
    const float* q_w      = (const float*)d_in[4];
    const float* k_w      = (const float*)d_in[5];
    const float* v_w      = (const float*)d_in[6];
    const float* o_w      = (const float*)d_in[7];
    const float* router_w = (const float*)d_in[8];
    const float* w1       = (const float*)d_in[9];
    const float* w2       = (const float*)d_in[10];
    const float* w3       = (const float*)d_in[11];
    float* out = (float*)d_out;

    float *xn, *xnr, *qb, *kb, *vb, *ctx, *h1, *a1, *a3, *coef;
    float *wqT, *wkT, *wvT, *woT, *w1T, *w2T, *w3T;
    int *cnt, *tokl, *aidl;
    cudaGetSymbolAddress((void**)&xn,   g_xn);
    cudaGetSymbolAddress((void**)&xnr,  g_xnr);
    cudaGetSymbolAddress((void**)&qb,   g_q);
    cudaGetSymbolAddress((void**)&kb,   g_k);
    cudaGetSymbolAddress((void**)&vb,   g_v);
    cudaGetSymbolAddress((void**)&ctx,  g_ctx);
    cudaGetSymbolAddress((void**)&h1,   g_h1);
    cudaGetSymbolAddress((void**)&a1,   g_a1);
    cudaGetSymbolAddress((void**)&a3,   g_a3);
    cudaGetSymbolAddress((void**)&coef, g_coef);
    cudaGetSymbolAddress((void**)&cnt,  g_cnt);
    cudaGetSymbolAddress((void**)&tokl, g_tok);
    cudaGetSymbolAddress((void**)&aidl, g_aid);
    cudaGetSymbolAddress((void**)&wqT,  g_wqT);
    cudaGetSymbolAddress((void**)&wkT,  g_wkT);
    cudaGetSymbolAddress((void**)&wvT,  g_wvT);
    cudaGetSymbolAddress((void**)&woT,  g_woT);
    cudaGetSymbolAddress((void**)&w1T,  g_w1T);
    cudaGetSymbolAddress((void**)&w2T,  g_w2T);
    cudaGetSymbolAddress((void**)&w3T,  g_w3T);

    cudaFuncSetAttribute(mma_gemm, cudaFuncAttributeMaxDynamicSharedMemorySize, MMA_SMEM);
    cudaFuncSetAttribute(flash_kernel, cudaFuncAttributeMaxDynamicSharedMemorySize, FLASH_SMEM);

    const dim3 tb(32, 8);
    // 0. transpose + tf32-round all weights into [N][K] layout
    wtrans_kernel<<<dim3(64, 64, 1), tb>>>(q_w, wqT);
    wtrans_kernel<<<dim3(64, 64, 1), tb>>>(k_w, wkT);
    wtrans_kernel<<<dim3(64, 64, 1), tb>>>(v_w, wvT);
    wtrans_kernel<<<dim3(64, 64, 1), tb>>>(o_w, woT);
    wtrans_kernel<<<dim3(64, 64, E_), tb>>>(w1, w1T);
    wtrans_kernel<<<dim3(64, 64, E_), tb>>>(w2, w2T);
    wtrans_kernel<<<dim3(64, 64, E_), tb>>>(w3, w3T);

    const dim3 dg(H_ / 128, T_ / 128, 1);     // (16, 32)
    const dim3 eg(H_ / 128, T_ / 128, E_);    // (16, 32, 8)

    // 1. pre-attention rmsnorm (rounded only)
    rmsnorm_kernel<<<T_, 256>>>(hidden, rms1_w, xnr, nullptr, nullptr);
    // 2. Q/K/V projections (tensor cores)
    mma_gemm<<<dg, 256, MMA_SMEM>>>(xnr, wqT, qb, nullptr, nullptr, nullptr, nullptr, nullptr,
                                    T_, H_, H_, 0);
    mma_gemm<<<dg, 256, MMA_SMEM>>>(xnr, wkT, kb, nullptr, nullptr, nullptr, nullptr, nullptr,
                                    T_, H_, H_, 0);
    mma_gemm<<<dg, 256, MMA_SMEM>>>(xnr, wvT, vb, nullptr, nullptr, nullptr, nullptr, nullptr,
                                    T_, H_, H_, 0);
    // 3. RoPE in place
    rope_kernel<<<(T_ * NH_ * 64) / 256, 256>>>(qb, kb, pos);
    // 4. causal flash attention (writes tf32-rounded ctx)
    flash_kernel<<<dim3(S_ / 64, NH_, 2), 512, FLASH_SMEM>>>(qb, kb, vb, ctx);
    // 5. O projection + residual
    mma_gemm<<<dg, 256, MMA_SMEM>>>(ctx, woT, h1, hidden, nullptr, nullptr, nullptr, nullptr,
                                    T_, H_, H_, 0);
    // 6. post-attention rmsnorm: rounded + exact (router) + seed out with h1
    rmsnorm_kernel<<<T_, 256>>>(h1, rms2_w, xnr, xn, out);
    // 7. routing
    zero_counts_kernel<<<1, 32>>>(cnt);
    router_kernel<<<T_, 256>>>(xn, router_w, cnt, tokl, aidl, coef);
    // 8. expert up-projections (gathered rows)
    mma_gemm<<<eg, 256, MMA_SMEM>>>(xnr, w1T, a1, nullptr, cnt, tokl, aidl, nullptr,
                                    T_, I_, H_, 1);
    mma_gemm<<<eg, 256, MMA_SMEM>>>(xnr, w3T, a3, nullptr, cnt, tokl, aidl, nullptr,
                                    T_, I_, H_, 1);
    // 9. fused activation
    silu_mul_kernel<<<(2 * T_ * I_ / 4 + 255) / 256, 256>>>((float4*)a1, (const float4*)a3,
                                                            2 * T_ * I_ / 4);
    // 10. down projection: atomic scatter coeff * result into out (= h1 + moe)
    mma_gemm<<<eg, 256, MMA_SMEM>>>(a1, w2T, out, nullptr, cnt, aidl, tokl, coef,
                                    T_, H_, I_, 2);
}

// round 13
// speedup vs baseline: 6.5502x; 3.4592x over previous
#include <cuda_runtime.h>
#include <math.h>
#include <float.h>
#include <stdint.h>

// Problem constants
#define T_   4096      // B*S tokens
#define H_   2048
#define S_   2048
#define NH_  16
#define HD_  128
#define E_   8
#define I_   2048
#define EPS_ 1e-5f
#define SCALE_ 0.08838834764831845f  // 1/sqrt(128)

// ---------------- scratch (static device globals; no allocations) ----------
__device__ float g_xn  [T_ * H_];      // rmsnorm2 exact (router input)
__device__ float g_xnr [T_ * H_];      // rmsnorm tf32-rounded (GEMM A)
__device__ float g_q   [T_ * H_];
__device__ float g_k   [T_ * H_];
__device__ float g_v   [T_ * H_];
__device__ float g_ctx [T_ * H_];
__device__ float g_h1  [T_ * H_];
__device__ float g_a1  [2 * T_ * I_];
__device__ float g_a3  [2 * T_ * I_];
__device__ int   g_cnt [E_];
__device__ int   g_tok [E_ * T_];
__device__ int   g_aid [E_ * T_];
__device__ float g_coef[E_ * T_];
// transposed + tf32-rounded weights ([N][K] K-major)
__device__ float g_wqT[H_ * H_], g_wkT[H_ * H_], g_wvT[H_ * H_], g_woT[H_ * H_];
__device__ float g_w1T[E_ * H_ * I_], g_w2T[E_ * I_ * H_], g_w3T[E_ * H_ * I_];

// ---------------- helpers --------------------------------------------------
__device__ __forceinline__ float tf32r(float x)
{
    unsigned r;
    asm("cvt.rna.tf32.f32 %0, %1;" : "=r"(r) : "f"(x));
    return __uint_as_float(r);
}
__device__ __forceinline__ unsigned smem_u32(const void* p)
{
    return (unsigned)__cvta_generic_to_shared(p);
}
__device__ __forceinline__ void cp16(uint32_t daddr, const void* src, int bytes)
{
    asm volatile("cp.async.cg.shared.global [%0], [%1], 16, %2;\n"
                 :: "r"(daddr), "l"(src), "r"(bytes));
}
__device__ __forceinline__ void ldsm4(unsigned& r0, unsigned& r1, unsigned& r2, unsigned& r3,
                                      uint32_t addr)
{
    asm volatile("ldmatrix.sync.aligned.m8n8.x4.shared.b16 {%0,%1,%2,%3}, [%4];\n"
                 : "=r"(r0), "=r"(r1), "=r"(r2), "=r"(r3) : "r"(addr));
}
__device__ __forceinline__ void mma_tf32(float* c, const unsigned* a, const unsigned* b)
{
    asm volatile(
        "mma.sync.aligned.m16n8k8.row.col.f32.tf32.tf32.f32 "
        "{%0,%1,%2,%3}, {%4,%5,%6,%7}, {%8,%9}, {%0,%1,%2,%3};\n"
        : "+f"(c[0]), "+f"(c[1]), "+f"(c[2]), "+f"(c[3])
        : "r"(a[0]), "r"(a[1]), "r"(a[2]), "r"(a[3]), "r"(b[0]), "r"(b[1]));
}

// ---------------- weight transpose + tf32 round ----------------------------
__device__ __forceinline__ void wtrans_body(const float* s, float* d)
{
    __shared__ float t[32][33];
    const int x0 = blockIdx.x * 32, y0 = blockIdx.y * 32;
    const int tx = threadIdx.x, ty = threadIdx.y;   // 32 x 8
#pragma unroll
    for (int j = 0; j < 4; j++)
        t[ty + 8 * j][tx] = s[(size_t)(y0 + ty + 8 * j) * H_ + x0 + tx];
    __syncthreads();
#pragma unroll
    for (int j = 0; j < 4; j++)
        d[(size_t)(x0 + ty + 8 * j) * H_ + y0 + tx] = tf32r(t[tx][ty + 8 * j]);
}
// 4 matrices in one launch (z selects) — keeps launch #5 == first mma_gemm for ncu
__global__ void wtrans4_kernel(const float* s0, const float* s1, const float* s2,
                               const float* s3, float* d0, float* d1, float* d2, float* d3)
{
    const int z = blockIdx.z;
    const float* s = (z == 0) ? s0 : (z == 1) ? s1 : (z == 2) ? s2 : s3;
    float*       d = (z == 0) ? d0 : (z == 1) ? d1 : (z == 2) ? d2 : d3;
    wtrans_body(s, d);
}
__global__ void wtrans_kernel(const float* __restrict__ S, float* __restrict__ D)
{
    const size_t mo = (size_t)blockIdx.z * H_ * H_;
    wtrans_body(S + mo, D + mo);
}

// ---------------- rmsnorm: rounded out (+ optional exact out + copy) -------
__global__ void rmsnorm_kernel(const float* __restrict__ x, const float* __restrict__ w,
                               float* __restrict__ outr, float* __restrict__ oute,
                               float* __restrict__ cpy)
{
    const int t   = blockIdx.x;
    const int tid = threadIdx.x;
    const float* xr = x + (size_t)t * H_;
    float4 v0 = *(const float4*)(xr + tid * 4);
    float4 v1 = *(const float4*)(xr + 1024 + tid * 4);
    float ss = v0.x*v0.x + v0.y*v0.y + v0.z*v0.z + v0.w*v0.w
             + v1.x*v1.x + v1.y*v1.y + v1.z*v1.z + v1.w*v1.w;
#pragma unroll
    for (int o = 16; o > 0; o >>= 1) ss += __shfl_down_sync(0xffffffffu, ss, o);
    __shared__ float wsum[8];
    __shared__ float rsh;
    if ((tid & 31) == 0) wsum[tid >> 5] = ss;
    __syncthreads();
    if (tid == 0) {
        float tot = 0.f;
#pragma unroll
        for (int i = 0; i < 8; i++) tot += wsum[i];
        rsh = rsqrtf(tot * (1.f / H_) + EPS_);
    }
    __syncthreads();
    const float r = rsh;
    float4 w0 = *(const float4*)(w + tid * 4);
    float4 w1 = *(const float4*)(w + 1024 + tid * 4);
    float4 o0 = make_float4(v0.x*r*w0.x, v0.y*r*w0.y, v0.z*r*w0.z, v0.w*r*w0.w);
    float4 o1 = make_float4(v1.x*r*w1.x, v1.y*r*w1.y, v1.z*r*w1.z, v1.w*r*w1.w);
    if (oute) {
        float* ep = oute + (size_t)t * H_;
        *(float4*)(ep + tid * 4)        = o0;
        *(float4*)(ep + 1024 + tid * 4) = o1;
    }
    float4 r0 = make_float4(tf32r(o0.x), tf32r(o0.y), tf32r(o0.z), tf32r(o0.w));
    float4 r1 = make_float4(tf32r(o1.x), tf32r(o1.y), tf32r(o1.z), tf32r(o1.w));
    float* op = outr + (size_t)t * H_;
    *(float4*)(op + tid * 4)        = r0;
    *(float4*)(op + 1024 + tid * 4) = r1;
    if (cpy) {
        float* cp = cpy + (size_t)t * H_;
        *(float4*)(cp + tid * 4)        = v0;
        *(float4*)(cp + 1024 + tid * 4) = v1;
    }
}

// ================= tf32 mma.sync GEMM (ldmatrix A and B) ====================
#define BK_   32
#define SA0_  0
#define SB0_  16384
#define SA1_  32768
#define SB1_  49152
#define MMA_SMEM 65536
#define SWOFF(row, ch) ((unsigned)(row) * 128u + (unsigned)(((ch) ^ ((row) & 7)) << 4))

__global__ __launch_bounds__(256, 2) void mma_gemm(
    const float* __restrict__ A, const float* __restrict__ BT,
    float* __restrict__ C, const float* __restrict__ addend,
    const int* __restrict__ counts, const int* __restrict__ arow_l,
    const int* __restrict__ crow_l, const float* __restrict__ cscale_l,
    int M, int N, int K, int mode)
{
    const int e   = blockIdx.z;
    const int cnt = counts ? counts[e] : M;
    const int m0  = blockIdx.y * 128;
    if (m0 >= cnt) return;
    const int n0  = blockIdx.x * 128;
    const float* Bt = BT + (size_t)e * K * N;
    const int*   ar = arow_l   ? arow_l   + e * T_ : nullptr;
    const int*   cr = crow_l   ? crow_l   + e * T_ : nullptr;
    const float* cs = cscale_l ? cscale_l + e * T_ : nullptr;

    extern __shared__ char smem[];
    const uint32_t sb = smem_u32(smem);
    const int tid = threadIdx.x, lane = tid & 31, warp = tid >> 5;
    const int wm = (warp >> 2) * 64, wn = (warp & 3) * 32;

    const int rbase = tid >> 3, ch0 = tid & 7;
    const float* aptr[4];
    int ab[4];
#pragma unroll
    for (int i = 0; i < 4; i++) {
        const int r  = m0 + rbase + 32 * i;
        const bool ok = (r < cnt);
        const int grow = ok ? (ar ? ar[r] : r) : 0;
        aptr[i] = A + (size_t)grow * K + ch0 * 4;
        ab[i]   = ok ? 16 : 0;
    }
    const float* bptr[4];
#pragma unroll
    for (int i = 0; i < 4; i++)
        bptr[i] = Bt + (size_t)(n0 + rbase + 32 * i) * K + ch0 * 4;

    auto load_stage = [&](int st, int k0) {
        const uint32_t abase = sb + (st ? SA1_ : SA0_);
        const uint32_t bbase = sb + (st ? SB1_ : SB0_);
#pragma unroll
        for (int i = 0; i < 4; i++)
            cp16(abase + SWOFF(rbase + 32 * i, ch0), aptr[i] + k0, ab[i]);
#pragma unroll
        for (int i = 0; i < 4; i++)
            cp16(bbase + SWOFF(rbase + 32 * i, ch0), bptr[i] + k0, 16);
        asm volatile("cp.async.commit_group;\n" ::: "memory");
    };

    float acc[4][4][4];
#pragma unroll
    for (int i = 0; i < 4; i++)
#pragma unroll
        for (int j = 0; j < 4; j++)
#pragma unroll
            for (int c = 0; c < 4; c++) acc[i][j][c] = 0.f;

    const int NIT = K / BK_;
    load_stage(0, 0);
    if (NIT > 1) load_stage(1, BK_);

    for (int it = 0; it < NIT; it++) {
        const int st = it & 1;
        if (it + 1 < NIT)
            asm volatile("cp.async.wait_group 1;\n" ::: "memory");
        else
            asm volatile("cp.async.wait_group 0;\n" ::: "memory");
        __syncthreads();
        const uint32_t abase = sb + (st ? SA1_ : SA0_);
        const uint32_t bbase = sb + (st ? SB1_ : SB0_);
#pragma unroll
        for (int ks = 0; ks < 4; ks++) {
            unsigned af[4][4];
#pragma unroll
            for (int i = 0; i < 4; i++) {
                const int row = wm + 16 * i + (lane & 7) + ((lane >> 3) & 1) * 8;
                const int ch  = ks * 2 + (lane >> 4);
                ldsm4(af[i][0], af[i][1], af[i][2], af[i][3], abase + SWOFF(row, ch));
            }
            unsigned bfr[4][2];
#pragma unroll
            for (int jj = 0; jj < 4; jj += 2) {
                const int q = lane >> 3;
                const int row = wn + 8 * jj + 8 * (q >> 1) + (lane & 7);
                const int ch  = ks * 2 + (q & 1);
                ldsm4(bfr[jj][0], bfr[jj][1], bfr[jj+1][0], bfr[jj+1][1],
                      bbase + SWOFF(row, ch));
            }
#pragma unroll
            for (int i = 0; i < 4; i++)
#pragma unroll
                for (int j = 0; j < 4; j++)
                    mma_tf32(acc[i][j], af[i], bfr[j]);
        }
        __syncthreads();
        if (it + 2 < NIT) load_stage(st, (it + 2) * BK_);
    }

    // ---------------- epilogue ----------------
#pragma unroll
    for (int i = 0; i < 4; i++) {
        const int lr0 = wm + 16 * i + (lane >> 2);
        const int gr0 = m0 + lr0, gr1 = gr0 + 8;
        const bool ok0 = gr0 < cnt, ok1 = gr1 < cnt;
        if (mode == 2) {
            const float s0 = ok0 ? cs[gr0] : 0.f;
            const float s1 = ok1 ? cs[gr1] : 0.f;
            const int   o0 = ok0 ? cr[gr0] : 0;
            const int   o1 = ok1 ? cr[gr1] : 0;
#pragma unroll
            for (int j = 0; j < 4; j++) {
                const int c = n0 + wn + 8 * j + 2 * (lane & 3);
                if (ok0) {
                    atomicAdd(&C[(size_t)o0 * N + c],     s0 * acc[i][j][0]);
                    atomicAdd(&C[(size_t)o0 * N + c + 1], s0 * acc[i][j][1]);
                }
                if (ok1) {
                    atomicAdd(&C[(size_t)o1 * N + c],     s1 * acc[i][j][2]);
                    atomicAdd(&C[(size_t)o1 * N + c + 1], s1 * acc[i][j][3]);
                }
            }
        } else if (mode == 1) {
            const int o0 = ok0 ? cr[gr0] : 0;
            const int o1 = ok1 ? cr[gr1] : 0;
#pragma unroll
            for (int j = 0; j < 4; j++) {
                const int c = n0 + wn + 8 * j + 2 * (lane & 3);
                if (ok0) *(float2*)&C[(size_t)o0 * N + c] = make_float2(acc[i][j][0], acc[i][j][1]);
                if (ok1) *(float2*)&C[(size_t)o1 * N + c] = make_float2(acc[i][j][2], acc[i][j][3]);
            }
        } else {
#pragma unroll
            for (int j = 0; j < 4; j++) {
                const int c = n0 + wn + 8 * j + 2 * (lane & 3);
                float2 v0 = make_float2(acc[i][j][0], acc[i][j][1]);
                float2 v1 = make_float2(acc[i][j][2], acc[i][j][3]);
                if (addend) {
                    float2 a0 = *(const float2*)&addend[(size_t)gr0 * N + c];
                    float2 a1 = *(const float2*)&addend[(size_t)gr1 * N + c];
                    v0.x += a0.x; v0.y += a0.y; v1.x += a1.x; v1.y += a1.y;
                }
                *(float2*)&C[(size_t)gr0 * N + c] = v0;
                *(float2*)&C[(size_t)gr1 * N + c] = v1;
            }
        }
    }
}

// ---------------- RoPE in-place + tf32 round of q, k, v --------------------
__global__ void rope_kernel(float* __restrict__ q, float* __restrict__ k,
                            float* __restrict__ v, const int* __restrict__ pos_ids)
{
    const int idx = blockIdx.x * blockDim.x + threadIdx.x;
    if (idx >= T_ * NH_ * 64) return;
    const int d  = idx & 63;
    const int hh = (idx >> 6) & (NH_ - 1);
    const int t  = idx >> 10;
    const float pos = (float)pos_ids[t];
    const float inv = expf(-0.14391156831212787f * (float)d);
    float sv, cv;
    sincosf(pos * inv, &sv, &cv);
    const size_t base = (size_t)t * H_ + hh * HD_ + d;
    float q1 = q[base], q2 = q[base + 64];
    q[base]      = tf32r(q1 * cv - q2 * sv);
    q[base + 64] = tf32r(q2 * cv + q1 * sv);
    float k1 = k[base], k2 = k[base + 64];
    k[base]      = tf32r(k1 * cv - k2 * sv);
    k[base + 64] = tf32r(k2 * cv + k1 * sv);
    v[base]      = tf32r(v[base]);
    v[base + 64] = tf32r(v[base + 64]);
}

// ============ causal flash attention v2 — tensor cores (tf32 mma) ==========
// Br=Bc=64, 256 threads = 8 warps as 4M x 2N.
// QK^T: warp tile 16x32; PV: warp tile 16x64 (hd). fp32 online softmax.
#define QST 132
#define KST 132
#define VST 136
#define PST 68
#define OQ   0
#define OK_  (OQ  + 64 * QST)     // 8448
#define OV_  (OK_ + 64 * KST)     // 16896
#define OP_  (OV_ + 64 * VST)     // 25600
#define ORED (OP_ + 64 * PST)     // 29952
#define OSUM (ORED + 128)         // 30080
#define OM_  (OSUM + 128)         // 30208
#define OL_  (OM_ + 64)           // 30272
#define FLASH2_SMEM ((OL_ + 64) * 4)   // 121344 B

__global__ __launch_bounds__(256, 1) void flash2_kernel(
    const float* __restrict__ q, const float* __restrict__ k,
    const float* __restrict__ v, float* __restrict__ ctx)
{
    extern __shared__ float sm[];
    const uint32_t sb = smem_u32(sm);
    const int qt = blockIdx.x, hh = blockIdx.y, b = blockIdx.z;
    const int tid = threadIdx.x, lane = tid & 31, w = tid >> 5;
    const int wm = (w & 3) * 16, wnh = w >> 2;
    const int wn = wnh * 32, wn2 = wnh * 64;
    const int rq = lane >> 2;                    // quad row in warp tile

    // load Q tile (already tf32-rounded)
    const size_t qbase = ((size_t)(b * S_ + qt * 64)) * H_ + hh * HD_;
#pragma unroll
    for (int i = 0; i < 8; i++) {
        const int id = tid + 256 * i;
        const int r = id >> 5, c4 = (id & 31) * 4;
        *(float4*)&sm[OQ + r * QST + c4] = *(const float4*)(q + qbase + (size_t)r * H_ + c4);
    }
    if (tid < 64) { sm[OM_ + tid] = -1e30f; sm[OL_ + tid] = 0.f; }

    float accO[8][4];
#pragma unroll
    for (int nf = 0; nf < 8; nf++)
#pragma unroll
        for (int c = 0; c < 4; c++) accO[nf][c] = 0.f;

    for (int kc = 0; kc <= qt; kc++) {
        __syncthreads();   // prior-tile consumers done (also orders OM_/OL_ writes)
        const size_t kbase = ((size_t)(b * S_ + kc * 64)) * H_ + hh * HD_;
#pragma unroll
        for (int i = 0; i < 8; i++) {
            const int id = tid + 256 * i;
            const int r = id >> 5, c4 = (id & 31) * 4;
            *(float4*)&sm[OK_ + r * KST + c4] = *(const float4*)(k + kbase + (size_t)r * H_ + c4);
            *(float4*)&sm[OV_ + r * VST + c4] = *(const float4*)(v + kbase + (size_t)r * H_ + c4);
        }
        __syncthreads();

        // ---- S = Q K^T ----
        float accS[4][4];
#pragma unroll
        for (int nf = 0; nf < 4; nf++)
#pragma unroll
            for (int c = 0; c < 4; c++) accS[nf][c] = 0.f;
#pragma unroll
        for (int ks = 0; ks < 16; ks++) {
            unsigned af[4];
            {
                const int row = wm + (lane & 7) + ((lane >> 3) & 1) * 8;
                const uint32_t addr = sb + 4u * (unsigned)(OQ + row * QST)
                                    + 16u * (unsigned)(2 * ks + (lane >> 4));
                ldsm4(af[0], af[1], af[2], af[3], addr);
            }
            unsigned bfr[4][2];
#pragma unroll
            for (int jj = 0; jj < 4; jj += 2) {
                const int qd = lane >> 3;
                const int row = wn + 8 * jj + 8 * (qd >> 1) + (lane & 7);
                const uint32_t addr = sb + 4u * (unsigned)(OK_ + row * KST)
                                    + 16u * (unsigned)(2 * ks + (qd & 1));
                ldsm4(bfr[jj][0], bfr[jj][1], bfr[jj+1][0], bfr[jj+1][1], addr);
            }
#pragma unroll
            for (int nf = 0; nf < 4; nf++)
                mma_tf32(accS[nf], af, bfr[nf]);
        }

        // ---- scale + causal mask ----
        const int rg0 = qt * 64 + wm + rq;       // global seq rows
        const bool diag = (kc == qt);
#pragma unroll
        for (int nf = 0; nf < 4; nf++) {
            const int col0 = kc * 64 + wn + 8 * nf + 2 * (lane & 3);
#pragma unroll
            for (int c = 0; c < 4; c++) {
                const int col = col0 + (c & 1);
                const int row = rg0 + ((c >> 1) << 3);
                float val = accS[nf][c] * SCALE_;
                if (diag && col > row) val = -1e30f;
                accS[nf][c] = val;
            }
        }

        // ---- row max (quad shfl + cross-warp smem) ----
        float mx0 = -1e30f, mx1 = -1e30f;
#pragma unroll
        for (int nf = 0; nf < 4; nf++) {
            mx0 = fmaxf(mx0, fmaxf(accS[nf][0], accS[nf][1]));
            mx1 = fmaxf(mx1, fmaxf(accS[nf][2], accS[nf][3]));
        }
#pragma unroll
        for (int o = 1; o <= 2; o <<= 1) {
            mx0 = fmaxf(mx0, __shfl_xor_sync(0xffffffffu, mx0, o));
            mx1 = fmaxf(mx1, __shfl_xor_sync(0xffffffffu, mx1, o));
        }
        if ((lane & 3) == 0) {
            sm[ORED + wnh * 64 + wm + rq]     = mx0;
            sm[ORED + wnh * 64 + wm + rq + 8] = mx1;
        }
        __syncthreads();

        const float mo0 = sm[OM_ + wm + rq];
        const float mo1 = sm[OM_ + wm + rq + 8];
        const float mn0 = fmaxf(mo0, fmaxf(sm[ORED + wm + rq],     sm[ORED + 64 + wm + rq]));
        const float mn1 = fmaxf(mo1, fmaxf(sm[ORED + wm + rq + 8], sm[ORED + 64 + wm + rq + 8]));
        const float al0 = __expf(mo0 - mn0);
        const float al1 = __expf(mo1 - mn1);
#pragma unroll
        for (int nf = 0; nf < 8; nf++) {
            accO[nf][0] *= al0; accO[nf][1] *= al0;
            accO[nf][2] *= al1; accO[nf][3] *= al1;
        }
        // ---- P = exp(S - m), stage to smem (tf32), partial row sums ----
        float s0 = 0.f, s1 = 0.f;
#pragma unroll
        for (int nf = 0; nf < 4; nf++) {
            const float p0 = __expf(accS[nf][0] - mn0);
            const float p1 = __expf(accS[nf][1] - mn0);
            const float p2 = __expf(accS[nf][2] - mn1);
            const float p3 = __expf(accS[nf][3] - mn1);
            s0 += p0 + p1; s1 += p2 + p3;
            const int pc = wn + 8 * nf + 2 * (lane & 3);
            *(float2*)&sm[OP_ + (wm + rq)     * PST + pc] = make_float2(tf32r(p0), tf32r(p1));
            *(float2*)&sm[OP_ + (wm + rq + 8) * PST + pc] = make_float2(tf32r(p2), tf32r(p3));
        }
#pragma unroll
        for (int o = 1; o <= 2; o <<= 1) {
            s0 += __shfl_xor_sync(0xffffffffu, s0, o);
            s1 += __shfl_xor_sync(0xffffffffu, s1, o);
        }
        if ((lane & 3) == 0) {
            sm[OSUM + wnh * 64 + wm + rq]     = s0;
            sm[OSUM + wnh * 64 + wm + rq + 8] = s1;
        }
        __syncthreads();

        if (w < 4 && (lane & 3) == 0) {
            int r = wm + rq;
            sm[OL_ + r] = sm[OL_ + r] * al0 + sm[OSUM + r] + sm[OSUM + 64 + r];
            sm[OM_ + r] = mn0;
            r += 8;
            sm[OL_ + r] = sm[OL_ + r] * al1 + sm[OSUM + r] + sm[OSUM + 64 + r];
            sm[OM_ + r] = mn1;
        }

        // ---- O += P V ----
#pragma unroll
        for (int ks = 0; ks < 8; ks++) {
            unsigned pf[4];
            {
                const int row = wm + (lane & 7) + ((lane >> 3) & 1) * 8;
                const uint32_t addr = sb + 4u * (unsigned)(OP_ + row * PST)
                                    + 16u * (unsigned)(2 * ks + (lane >> 4));
                ldsm4(pf[0], pf[1], pf[2], pf[3], addr);
            }
            const int kv0 = ks * 8 + (lane & 3);
            const float* v0p = &sm[OV_ + kv0 * VST + wn2 + (lane >> 2)];
            const float* v1p = v0p + 4 * VST;
#pragma unroll
            for (int nf = 0; nf < 8; nf++) {
                unsigned bv[2];
                bv[0] = __float_as_uint(v0p[8 * nf]);
                bv[1] = __float_as_uint(v1p[8 * nf]);
                mma_tf32(accO[nf], pf, bv);
            }
        }
    }

    __syncthreads();
    const float li0 = 1.f / sm[OL_ + wm + rq];
    const float li1 = 1.f / sm[OL_ + wm + rq + 8];
    const size_t obase = ((size_t)(b * S_ + qt * 64)) * H_ + hh * HD_;
#pragma unroll
    for (int nf = 0; nf < 8; nf++) {
        const int col = wn2 + 8 * nf + 2 * (lane & 3);
        float* op0 = ctx + obase + (size_t)(wm + rq) * H_ + col;
        float* op1 = ctx + obase + (size_t)(wm + rq + 8) * H_ + col;
        *(float2*)op0 = make_float2(tf32r(accO[nf][0] * li0), tf32r(accO[nf][1] * li0));
        *(float2*)op1 = make_float2(tf32r(accO[nf][2] * li1), tf32r(accO[nf][3] * li1));
    }
}

// ---------------- router ---------------------------------------------------
__global__ void zero_counts_kernel(int* c)
{
    if (threadIdx.x < E_) c[threadIdx.x] = 0;
}

__global__ void router_kernel(const float* __restrict__ xn, const float* __restrict__ rw,
                              int* __restrict__ counts, int* __restrict__ tok,
                              int* __restrict__ aid, float* __restrict__ coef)
{
    const int t = blockIdx.x;
    const int tid = threadIdx.x;
    float a[8] = {0.f,0.f,0.f,0.f,0.f,0.f,0.f,0.f};
    const float* xr = xn + (size_t)t * H_;
    for (int kk = tid; kk < H_; kk += 256) {
        const float xv = xr[kk];
        float4 r0 = *(const float4*)(rw + kk * 8);
        float4 r1 = *(const float4*)(rw + kk * 8 + 4);
        a[0] += xv * r0.x; a[1] += xv * r0.y; a[2] += xv * r0.z; a[3] += xv * r0.w;
        a[4] += xv * r1.x; a[5] += xv * r1.y; a[6] += xv * r1.z; a[7] += xv * r1.w;
    }
#pragma unroll
    for (int o = 16; o > 0; o >>= 1)
#pragma unroll
        for (int e = 0; e < 8; e++) a[e] += __shfl_down_sync(0xffffffffu, a[e], o);
    __shared__ float ws[8][8];
    if ((tid & 31) == 0)
#pragma unroll
        for (int e = 0; e < 8; e++) ws[tid >> 5][e] = a[e];
    __syncthreads();
    if (tid == 0) {
        float lg[8];
#pragma unroll
        for (int e = 0; e < 8; e++) {
            float s = 0.f;
#pragma unroll
            for (int w = 0; w < 8; w++) s += ws[w][e];
            lg[e] = s;
        }
        int i1 = 0;
#pragma unroll
        for (int e = 1; e < 8; e++) if (lg[e] > lg[i1]) i1 = e;
        int i2 = (i1 == 0) ? 1 : 0;
#pragma unroll
        for (int e = 0; e < 8; e++) if (e != i1 && lg[e] > lg[i2]) i2 = e;
        const float ex = expf(lg[i2] - lg[i1]);
        const float c1 = 1.f / (1.f + ex);
        const float c2 = ex / (1.f + ex);
        int s1 = atomicAdd(&counts[i1], 1);
        tok[i1 * T_ + s1] = t; aid[i1 * T_ + s1] = 2 * t;     coef[i1 * T_ + s1] = c1;
        int s2 = atomicAdd(&counts[i2], 1);
        tok[i2 * T_ + s2] = t; aid[i2 * T_ + s2] = 2 * t + 1; coef[i2 * T_ + s2] = c2;
    }
}

// ---------------- fused SiLU * gate (tf32-rounded output) ------------------
__global__ void silu_mul_kernel(float4* __restrict__ a1, const float4* __restrict__ a3, int n4)
{
    const int i = blockIdx.x * blockDim.x + threadIdx.x;
    if (i >= n4) return;
    float4 g = a1[i];
    float4 u = a3[i];
    g.x = tf32r((g.x / (1.f + __expf(-g.x))) * u.x);
    g.y = tf32r((g.y / (1.f + __expf(-g.y))) * u.y);
    g.z = tf32r((g.z / (1.f + __expf(-g.z))) * u.z);
    g.w = tf32r((g.w / (1.f + __expf(-g.w))) * u.w);
    a1[i] = g;
}

// ---------------- launcher -------------------------------------------------
extern "C" void kernel_launch(void* const* d_in, const int* in_sizes, int n_in,
                              void* d_out, int out_size)
{
    const float* hidden   = (const float*)d_in[0];
    const int*   pos      = (const int*)  d_in[1];
    const float* rms1_w   = (const float*)d_in[2];
    const float* rms2_w   = (const float*)d_in[3];
    const float* q_w      = (const float*)d_in[4];
    const float* k_w      = (const float*)d_in[5];
    const float* v_w      = (const float*)d_in[6];
    const float* o_w      = (const float*)d_in[7];
    const float* router_w = (const float*)d_in[8];
    const float* w1       = (const float*)d_in[9];
    const float* w2       = (const float*)d_in[10];
    const float* w3       = (const float*)d_in[11];
    float* out = (float*)d_out;

    float *xn, *xnr, *qb, *kb, *vb, *ctx, *h1, *a1, *a3, *coef;
    float *wqT, *wkT, *wvT, *woT, *w1T, *w2T, *w3T;
    int *cnt, *tokl, *aidl;
    cudaGetSymbolAddress((void**)&xn,   g_xn);
    cudaGetSymbolAddress((void**)&xnr,  g_xnr);
    cudaGetSymbolAddress((void**)&qb,   g_q);
    cudaGetSymbolAddress((void**)&kb,   g_k);
    cudaGetSymbolAddress((void**)&vb,   g_v);
    cudaGetSymbolAddress((void**)&ctx,  g_ctx);
    cudaGetSymbolAddress((void**)&h1,   g_h1);
    cudaGetSymbolAddress((void**)&a1,   g_a1);
    cudaGetSymbolAddress((void**)&a3,   g_a3);
    cudaGetSymbolAddress((void**)&coef, g_coef);
    cudaGetSymbolAddress((void**)&cnt,  g_cnt);
    cudaGetSymbolAddress((void**)&tokl, g_tok);
    cudaGetSymbolAddress((void**)&aidl, g_aid);
    cudaGetSymbolAddress((void**)&wqT,  g_wqT);
    cudaGetSymbolAddress((void**)&wkT,  g_wkT);
    cudaGetSymbolAddress((void**)&wvT,  g_wvT);
    cudaGetSymbolAddress((void**)&woT,  g_woT);
    cudaGetSymbolAddress((void**)&w1T,  g_w1T);
    cudaGetSymbolAddress((void**)&w2T,  g_w2T);
    cudaGetSymbolAddress((void**)&w3T,  g_w3T);

    cudaFuncSetAttribute(mma_gemm, cudaFuncAttributeMaxDynamicSharedMemorySize, MMA_SMEM);
    cudaFuncSetAttribute(flash2_kernel, cudaFuncAttributeMaxDynamicSharedMemorySize, FLASH2_SMEM);

    const dim3 tb(32, 8);
    // 0. transpose + tf32-round weights ([N][K]); qkvo fused into ONE launch
    wtrans4_kernel<<<dim3(64, 64, 4), tb>>>(q_w, k_w, v_w, o_w, wqT, wkT, wvT, woT);
    wtrans_kernel<<<dim3(64, 64, E_), tb>>>(w1, w1T);
    wtrans_kernel<<<dim3(64, 64, E_), tb>>>(w2, w2T);
    wtrans_kernel<<<dim3(64, 64, E_), tb>>>(w3, w3T);

    const dim3 dg(H_ / 128, T_ / 128, 1);     // (16, 32)
    const dim3 eg(H_ / 128, T_ / 128, E_);    // (16, 32, 8)

    // 1. pre-attention rmsnorm (rounded only)
    rmsnorm_kernel<<<T_, 256>>>(hidden, rms1_w, xnr, nullptr, nullptr);
    // 2. Q/K/V projections (tensor cores)  [launch #5 = first mma_gemm -> ncu target]
    mma_gemm<<<dg, 256, MMA_SMEM>>>(xnr, wqT, qb, nullptr, nullptr, nullptr, nullptr, nullptr,
                                    T_, H_, H_, 0);
    mma_gemm<<<dg, 256, MMA_SMEM>>>(xnr, wkT, kb, nullptr, nullptr, nullptr, nullptr, nullptr,
                                    T_, H_, H_, 0);
    mma_gemm<<<dg, 256, MMA_SMEM>>>(xnr, wvT, vb, nullptr, nullptr, nullptr, nullptr, nullptr,
                                    T_, H_, H_, 0);
    // 3. RoPE + tf32-round q/k/v
    rope_kernel<<<(T_ * NH_ * 64) / 256, 256>>>(qb, kb, vb, pos);
    // 4. causal flash attention on tensor cores (writes tf32-rounded ctx)
    flash2_kernel<<<dim3(S_ / 64, NH_, 2), 256, FLASH2_SMEM>>>(qb, kb, vb, ctx);
    // 5. O projection + residual
    mma_gemm<<<dg, 256, MMA_SMEM>>>(ctx, woT, h1, hidden, nullptr, nullptr, nullptr, nullptr,
                                    T_, H_, H_, 0);
    // 6. post-attention rmsnorm: rounded + exact (router) + seed out with h1
    rmsnorm_kernel<<<T_, 256>>>(h1, rms2_w, xnr, xn, out);
    // 7. routing
    zero_counts_kernel<<<1, 32>>>(cnt);
    router_kernel<<<T_, 256>>>(xn, router_w, cnt, tokl, aidl, coef);
    // 8. expert up-projections (gathered rows)
    mma_gemm<<<eg, 256, MMA_SMEM>>>(xnr, w1T, a1, nullptr, cnt, tokl, aidl, nullptr,
                                    T_, I_, H_, 1);
    mma_gemm<<<eg, 256, MMA_SMEM>>>(xnr, w3T, a3, nullptr, cnt, tokl, aidl, nullptr,
                                    T_, I_, H_, 1);
    // 9. fused activation
    silu_mul_kernel<<<(2 * T_ * I_ / 4 + 255) / 256, 256>>>((float4*)a1, (const float4*)a3,
                                                            2 * T_ * I_ / 4);
    // 10. down projection: atomic scatter coeff * result into out (= h1 + moe)
    mma_gemm<<<eg, 256, MMA_SMEM>>>(a1, w2T, out, nullptr, cnt, aidl, tokl, coef,
                                    T_, H_, I_, 2);
}

// round 16
// speedup vs baseline: 6.9593x; 1.0625x over previous
#include <cuda_runtime.h>
#include <math.h>
#include <float.h>
#include <stdint.h>

// Problem constants
#define T_   4096      // B*S tokens
#define H_   2048
#define S_   2048
#define NH_  16
#define HD_  128
#define E_   8
#define I_   2048
#define EPS_ 1e-5f
#define SCALE_ 0.08838834764831845f  // 1/sqrt(128)

// ---------------- scratch (static device globals; no allocations) ----------
__device__ float g_xn  [T_ * H_];          // rmsnorm2 exact (router input)
__device__ float g_xnr [T_ * H_];          // rmsnorm tf32-rounded (GEMM A)
__device__ float g_qkv [T_ * 3 * H_];      // fused QKV, row stride 6144
__device__ float g_ctx [T_ * H_];
__device__ float g_h1  [T_ * H_];
__device__ float g_a13 [2 * T_ * 2 * I_];  // fused up-proj out [8192][4096]
__device__ float g_a1  [2 * T_ * I_];      // silu(a1)*a3     [8192][2048]
__device__ int   g_cnt [E_];
__device__ int   g_tok [E_ * T_];
__device__ int   g_aid [E_ * T_];
__device__ float g_coef[E_ * T_];
// transposed + tf32-rounded weights (K-major rows)
__device__ float g_wqkvT[3 * H_ * H_];     // [6144][2048]
__device__ float g_woT  [H_ * H_];
__device__ float g_w13T [E_ * 2 * I_ * H_]; // per-e: rows 0..2047 w1, 2048..4095 w3
__device__ float g_w2T  [E_ * I_ * H_];

// ---------------- helpers --------------------------------------------------
__device__ __forceinline__ float tf32r(float x)
{
    unsigned r;
    asm("cvt.rna.tf32.f32 %0, %1;" : "=r"(r) : "f"(x));
    return __uint_as_float(r);
}
__device__ __forceinline__ unsigned smem_u32(const void* p)
{
    return (unsigned)__cvta_generic_to_shared(p);
}
__device__ __forceinline__ void cp16(uint32_t daddr, const void* src, int bytes)
{
    asm volatile("cp.async.cg.shared.global [%0], [%1], 16, %2;\n"
                 :: "r"(daddr), "l"(src), "r"(bytes));
}
__device__ __forceinline__ void ldsm4(unsigned& r0, unsigned& r1, unsigned& r2, unsigned& r3,
                                      uint32_t addr)
{
    asm volatile("ldmatrix.sync.aligned.m8n8.x4.shared.b16 {%0,%1,%2,%3}, [%4];\n"
                 : "=r"(r0), "=r"(r1), "=r"(r2), "=r"(r3) : "r"(addr));
}
__device__ __forceinline__ void mma_tf32(float* c, const unsigned* a, const unsigned* b)
{
    asm volatile(
        "mma.sync.aligned.m16n8k8.row.col.f32.tf32.tf32.f32 "
        "{%0,%1,%2,%3}, {%4,%5,%6,%7}, {%8,%9}, {%0,%1,%2,%3};\n"
        : "+f"(c[0]), "+f"(c[1]), "+f"(c[2]), "+f"(c[3])
        : "r"(a[0]), "r"(a[1]), "r"(a[2]), "r"(a[3]), "r"(b[0]), "r"(b[1]));
}

// ---------------- weight transpose + tf32 round ----------------------------
__device__ __forceinline__ void wtrans_body(const float* s, float* d)
{
    __shared__ float t[32][33];
    const int x0 = blockIdx.x * 32, y0 = blockIdx.y * 32;
    const int tx = threadIdx.x, ty = threadIdx.y;   // 32 x 8
#pragma unroll
    for (int j = 0; j < 4; j++)
        t[ty + 8 * j][tx] = s[(size_t)(y0 + ty + 8 * j) * H_ + x0 + tx];
    __syncthreads();
#pragma unroll
    for (int j = 0; j < 4; j++)
        d[(size_t)(x0 + ty + 8 * j) * H_ + y0 + tx] = tf32r(t[tx][ty + 8 * j]);
}
// q/k/v -> one concatenated [6144][2048] + o separate
__global__ void wtrans4_kernel(const float* s0, const float* s1, const float* s2,
                               const float* s3, float* dqkv, float* dO)
{
    const int z = blockIdx.z;
    const float* s = (z == 0) ? s0 : (z == 1) ? s1 : (z == 2) ? s2 : s3;
    float* d = (z == 3) ? dO : (dqkv + (size_t)z * H_ * H_);
    wtrans_body(s, d);
}
// w1 (z<E) and w3 (z>=E) -> combined per-expert [4096][2048]
__global__ void wtrans13_kernel(const float* w1, const float* w3, float* D)
{
    const int z = blockIdx.z;
    const float* s;
    float* d;
    if (z < E_) {
        s = w1 + (size_t)z * H_ * I_;
        d = D + (size_t)z * 2 * I_ * H_;
    } else {
        s = w3 + (size_t)(z - E_) * H_ * I_;
        d = D + (size_t)(z - E_) * 2 * I_ * H_ + (size_t)I_ * H_;
    }
    wtrans_body(s, d);
}
__global__ void wtrans_kernel(const float* __restrict__ S, float* __restrict__ D)
{
    const size_t mo = (size_t)blockIdx.z * H_ * H_;
    wtrans_body(S + mo, D + mo);
}

// ---------------- rmsnorm: rounded out (+ optional exact out + copy) -------
__global__ void rmsnorm_kernel(const float* __restrict__ x, const float* __restrict__ w,
                               float* __restrict__ outr, float* __restrict__ oute,
                               float* __restrict__ cpy)
{
    const int t   = blockIdx.x;
    const int tid = threadIdx.x;
    const float* xr = x + (size_t)t * H_;
    float4 v0 = *(const float4*)(xr + tid * 4);
    float4 v1 = *(const float4*)(xr + 1024 + tid * 4);
    float ss = v0.x*v0.x + v0.y*v0.y + v0.z*v0.z + v0.w*v0.w
             + v1.x*v1.x + v1.y*v1.y + v1.z*v1.z + v1.w*v1.w;
#pragma unroll
    for (int o = 16; o > 0; o >>= 1) ss += __shfl_down_sync(0xffffffffu, ss, o);
    __shared__ float wsum[8];
    __shared__ float rsh;
    if ((tid & 31) == 0) wsum[tid >> 5] = ss;
    __syncthreads();
    if (tid == 0) {
        float tot = 0.f;
#pragma unroll
        for (int i = 0; i < 8; i++) tot += wsum[i];
        rsh = rsqrtf(tot * (1.f / H_) + EPS_);
    }
    __syncthreads();
    const float r = rsh;
    float4 w0 = *(const float4*)(w + tid * 4);
    float4 w1 = *(const float4*)(w + 1024 + tid * 4);
    float4 o0 = make_float4(v0.x*r*w0.x, v0.y*r*w0.y, v0.z*r*w0.z, v0.w*r*w0.w);
    float4 o1 = make_float4(v1.x*r*w1.x, v1.y*r*w1.y, v1.z*r*w1.z, v1.w*r*w1.w);
    if (oute) {
        float* ep = oute + (size_t)t * H_;
        *(float4*)(ep + tid * 4)        = o0;
        *(float4*)(ep + 1024 + tid * 4) = o1;
    }
    float4 r0 = make_float4(tf32r(o0.x), tf32r(o0.y), tf32r(o0.z), tf32r(o0.w));
    float4 r1 = make_float4(tf32r(o1.x), tf32r(o1.y), tf32r(o1.z), tf32r(o1.w));
    float* op = outr + (size_t)t * H_;
    *(float4*)(op + tid * 4)        = r0;
    *(float4*)(op + 1024 + tid * 4) = r1;
    if (cpy) {
        float* cp = cpy + (size_t)t * H_;
        *(float4*)(cp + tid * 4)        = v0;
        *(float4*)(cp + 1024 + tid * 4) = v1;
    }
}

// ====== tf32 mma.sync GEMM, 3-stage cp.async pipeline (1 sync/iter) ========
#define BK_   32
#define STGB_ 32768                       // bytes per stage (A 16K + B 16K)
#define MMA_SMEM (3 * STGB_)              // 98304
#define SWOFF(row, ch) ((unsigned)(row) * 128u + (unsigned)(((ch) ^ ((row) & 7)) << 4))

__global__ __launch_bounds__(256, 2) void mma_gemm(
    const float* __restrict__ A, const float* __restrict__ BT,
    float* __restrict__ C, const float* __restrict__ addend,
    const int* __restrict__ counts, const int* __restrict__ arow_l,
    const int* __restrict__ crow_l, const float* __restrict__ cscale_l,
    int M, int N, int K, int mode)
{
    const int e   = blockIdx.z;
    const int cnt = counts ? counts[e] : M;
    const int m0  = blockIdx.y * 128;
    if (m0 >= cnt) return;
    const int n0  = blockIdx.x * 128;
    const float* Bt = BT + (size_t)e * K * N;
    const int*   ar = arow_l   ? arow_l   + e * T_ : nullptr;
    const int*   cr = crow_l   ? crow_l   + e * T_ : nullptr;
    const float* cs = cscale_l ? cscale_l + e * T_ : nullptr;

    extern __shared__ char smem[];
    const uint32_t sb = smem_u32(smem);
    const int tid = threadIdx.x, lane = tid & 31, warp = tid >> 5;
    const int wm = (warp >> 2) * 64, wn = (warp & 3) * 32;

    const int rbase = tid >> 3, ch0 = tid & 7;
    const float* aptr[4];
    int ab[4];
#pragma unroll
    for (int i = 0; i < 4; i++) {
        const int r  = m0 + rbase + 32 * i;
        const bool ok = (r < cnt);
        const int grow = ok ? (ar ? ar[r] : r) : 0;
        aptr[i] = A + (size_t)grow * K + ch0 * 4;
        ab[i]   = ok ? 16 : 0;
    }
    const float* bptr[4];
#pragma unroll
    for (int i = 0; i < 4; i++)
        bptr[i] = Bt + (size_t)(n0 + rbase + 32 * i) * K + ch0 * 4;

    auto load_stage = [&](int st, int k0) {
        const uint32_t abase = sb + st * STGB_;
        const uint32_t bbase = abase + 16384;
#pragma unroll
        for (int i = 0; i < 4; i++)
            cp16(abase + SWOFF(rbase + 32 * i, ch0), aptr[i] + k0, ab[i]);
#pragma unroll
        for (int i = 0; i < 4; i++)
            cp16(bbase + SWOFF(rbase + 32 * i, ch0), bptr[i] + k0, 16);
        asm volatile("cp.async.commit_group;\n" ::: "memory");
    };

    float acc[4][4][4];
#pragma unroll
    for (int i = 0; i < 4; i++)
#pragma unroll
        for (int j = 0; j < 4; j++)
#pragma unroll
            for (int c = 0; c < 4; c++) acc[i][j][c] = 0.f;

    const int NIT = K / BK_;                // >= 2 always here
    load_stage(0, 0);
    load_stage(1, BK_);

    for (int it = 0; it < NIT; it++) {
        const int st = it % 3;
        if (it + 1 < NIT)
            asm volatile("cp.async.wait_group 1;\n" ::: "memory");
        else
            asm volatile("cp.async.wait_group 0;\n" ::: "memory");
        __syncthreads();
        // prefetch stage it+2 into buffer (it+2)%3 == buffer read at it-1 (safe past barrier)
        if (it + 2 < NIT) load_stage((it + 2) % 3, (it + 2) * BK_);

        const uint32_t abase = sb + st * STGB_;
        const uint32_t bbase = abase + 16384;
#pragma unroll
        for (int ks = 0; ks < 4; ks++) {
            unsigned af[4][4];
#pragma unroll
            for (int i = 0; i < 4; i++) {
                const int row = wm + 16 * i + (lane & 7) + ((lane >> 3) & 1) * 8;
                const int ch  = ks * 2 + (lane >> 4);
                ldsm4(af[i][0], af[i][1], af[i][2], af[i][3], abase + SWOFF(row, ch));
            }
            unsigned bfr[4][2];
#pragma unroll
            for (int jj = 0; jj < 4; jj += 2) {
                const int q = lane >> 3;
                const int row = wn + 8 * jj + 8 * (q >> 1) + (lane & 7);
                const int ch  = ks * 2 + (q & 1);
                ldsm4(bfr[jj][0], bfr[jj][1], bfr[jj+1][0], bfr[jj+1][1],
                      bbase + SWOFF(row, ch));
            }
#pragma unroll
            for (int i = 0; i < 4; i++)
#pragma unroll
                for (int j = 0; j < 4; j++)
                    mma_tf32(acc[i][j], af[i], bfr[j]);
        }
    }

    // ---------------- epilogue ----------------
#pragma unroll
    for (int i = 0; i < 4; i++) {
        const int lr0 = wm + 16 * i + (lane >> 2);
        const int gr0 = m0 + lr0, gr1 = gr0 + 8;
        const bool ok0 = gr0 < cnt, ok1 = gr1 < cnt;
        if (mode == 2) {
            const float s0 = ok0 ? cs[gr0] : 0.f;
            const float s1 = ok1 ? cs[gr1] : 0.f;
            const int   o0 = ok0 ? cr[gr0] : 0;
            const int   o1 = ok1 ? cr[gr1] : 0;
#pragma unroll
            for (int j = 0; j < 4; j++) {
                const int c = n0 + wn + 8 * j + 2 * (lane & 3);
                if (ok0) {
                    atomicAdd(&C[(size_t)o0 * N + c],     s0 * acc[i][j][0]);
                    atomicAdd(&C[(size_t)o0 * N + c + 1], s0 * acc[i][j][1]);
                }
                if (ok1) {
                    atomicAdd(&C[(size_t)o1 * N + c],     s1 * acc[i][j][2]);
                    atomicAdd(&C[(size_t)o1 * N + c + 1], s1 * acc[i][j][3]);
                }
            }
        } else if (mode == 1) {
            const int o0 = ok0 ? cr[gr0] : 0;
            const int o1 = ok1 ? cr[gr1] : 0;
#pragma unroll
            for (int j = 0; j < 4; j++) {
                const int c = n0 + wn + 8 * j + 2 * (lane & 3);
                if (ok0) *(float2*)&C[(size_t)o0 * N + c] = make_float2(acc[i][j][0], acc[i][j][1]);
                if (ok1) *(float2*)&C[(size_t)o1 * N + c] = make_float2(acc[i][j][2], acc[i][j][3]);
            }
        } else {
#pragma unroll
            for (int j = 0; j < 4; j++) {
                const int c = n0 + wn + 8 * j + 2 * (lane & 3);
                float2 v0 = make_float2(acc[i][j][0], acc[i][j][1]);
                float2 v1 = make_float2(acc[i][j][2], acc[i][j][3]);
                if (addend) {
                    float2 a0 = *(const float2*)&addend[(size_t)gr0 * N + c];
                    float2 a1 = *(const float2*)&addend[(size_t)gr1 * N + c];
                    v0.x += a0.x; v0.y += a0.y; v1.x += a1.x; v1.y += a1.y;
                }
                *(float2*)&C[(size_t)gr0 * N + c] = v0;
                *(float2*)&C[(size_t)gr1 * N + c] = v1;
            }
        }
    }
}

// -------- RoPE in-place + tf32 round on fused qkv (row stride 6144) --------
__global__ void rope_kernel(float* __restrict__ qkv, const int* __restrict__ pos_ids)
{
    const int idx = blockIdx.x * blockDim.x + threadIdx.x;
    if (idx >= T_ * NH_ * 64) return;
    const int d  = idx & 63;
    const int hh = (idx >> 6) & (NH_ - 1);
    const int t  = idx >> 10;
    const float pos = (float)pos_ids[t];
    const float inv = expf(-0.14391156831212787f * (float)d);
    float sv, cv;
    sincosf(pos * inv, &sv, &cv);
    const size_t base = (size_t)t * (3 * H_) + hh * HD_ + d;
    float q1 = qkv[base], q2 = qkv[base + 64];
    qkv[base]      = tf32r(q1 * cv - q2 * sv);
    qkv[base + 64] = tf32r(q2 * cv + q1 * sv);
    float k1 = qkv[base + H_], k2 = qkv[base + H_ + 64];
    qkv[base + H_]      = tf32r(k1 * cv - k2 * sv);
    qkv[base + H_ + 64] = tf32r(k2 * cv + k1 * sv);
    qkv[base + 2 * H_]      = tf32r(qkv[base + 2 * H_]);
    qkv[base + 2 * H_ + 64] = tf32r(qkv[base + 2 * H_ + 64]);
}

// ============ causal flash attention v2 — tensor cores (tf32 mma) ==========
#define QRS (3 * H_)              // qkv row stride
#define QST 132
#define KST 132
#define VST 136
#define PST 68
#define OQ   0
#define OK_  (OQ  + 64 * QST)
#define OV_  (OK_ + 64 * KST)
#define OP_  (OV_ + 64 * VST)
#define ORED (OP_ + 64 * PST)
#define OSUM (ORED + 128)
#define OM_  (OSUM + 128)
#define OL_  (OM_ + 64)
#define FLASH2_SMEM ((OL_ + 64) * 4)   // 121344 B

__global__ __launch_bounds__(256, 1) void flash2_kernel(
    const float* __restrict__ qkv, float* __restrict__ ctx)
{
    extern __shared__ float sm[];
    const uint32_t sb = smem_u32(sm);
    const int qt = blockIdx.x, hh = blockIdx.y, b = blockIdx.z;
    const int tid = threadIdx.x, lane = tid & 31, w = tid >> 5;
    const int wm = (w & 3) * 16, wnh = w >> 2;
    const int wn = wnh * 32, wn2 = wnh * 64;
    const int rq = lane >> 2;

    const size_t qbase = ((size_t)(b * S_ + qt * 64)) * QRS + hh * HD_;
#pragma unroll
    for (int i = 0; i < 8; i++) {
        const int id = tid + 256 * i;
        const int r = id >> 5, c4 = (id & 31) * 4;
        *(float4*)&sm[OQ + r * QST + c4] = *(const float4*)(qkv + qbase + (size_t)r * QRS + c4);
    }
    if (tid < 64) { sm[OM_ + tid] = -1e30f; sm[OL_ + tid] = 0.f; }

    float accO[8][4];
#pragma unroll
    for (int nf = 0; nf < 8; nf++)
#pragma unroll
        for (int c = 0; c < 4; c++) accO[nf][c] = 0.f;

    for (int kc = 0; kc <= qt; kc++) {
        __syncthreads();
        const size_t kbase = ((size_t)(b * S_ + kc * 64)) * QRS + hh * HD_ + H_;
#pragma unroll
        for (int i = 0; i < 8; i++) {
            const int id = tid + 256 * i;
            const int r = id >> 5, c4 = (id & 31) * 4;
            const float* kp = qkv + kbase + (size_t)r * QRS + c4;
            *(float4*)&sm[OK_ + r * KST + c4] = *(const float4*)kp;
            *(float4*)&sm[OV_ + r * VST + c4] = *(const float4*)(kp + H_);
        }
        __syncthreads();

        float accS[4][4];
#pragma unroll
        for (int nf = 0; nf < 4; nf++)
#pragma unroll
            for (int c = 0; c < 4; c++) accS[nf][c] = 0.f;
#pragma unroll
        for (int ks = 0; ks < 16; ks++) {
            unsigned af[4];
            {
                const int row = wm + (lane & 7) + ((lane >> 3) & 1) * 8;
                const uint32_t addr = sb + 4u * (unsigned)(OQ + row * QST)
                                    + 16u * (unsigned)(2 * ks + (lane >> 4));
                ldsm4(af[0], af[1], af[2], af[3], addr);
            }
            unsigned bfr[4][2];
#pragma unroll
            for (int jj = 0; jj < 4; jj += 2) {
                const int qd = lane >> 3;
                const int row = wn + 8 * jj + 8 * (qd >> 1) + (lane & 7);
                const uint32_t addr = sb + 4u * (unsigned)(OK_ + row * KST)
                                    + 16u * (unsigned)(2 * ks + (qd & 1));
                ldsm4(bfr[jj][0], bfr[jj][1], bfr[jj+1][0], bfr[jj+1][1], addr);
            }
#pragma unroll
            for (int nf = 0; nf < 4; nf++)
                mma_tf32(accS[nf], af, bfr[nf]);
        }

        const int rg0 = qt * 64 + wm + rq;
        const bool diag = (kc == qt);
#pragma unroll
        for (int nf = 0; nf < 4; nf++) {
            const int col0 = kc * 64 + wn + 8 * nf + 2 * (lane & 3);
#pragma unroll
            for (int c = 0; c < 4; c++) {
                const int col = col0 + (c & 1);
                const int row = rg0 + ((c >> 1) << 3);
                float val = accS[nf][c] * SCALE_;
                if (diag && col > row) val = -1e30f;
                accS[nf][c] = val;
            }
        }

        float mx0 = -1e30f, mx1 = -1e30f;
#pragma unroll
        for (int nf = 0; nf < 4; nf++) {
            mx0 = fmaxf(mx0, fmaxf(accS[nf][0], accS[nf][1]));
            mx1 = fmaxf(mx1, fmaxf(accS[nf][2], accS[nf][3]));
        }
#pragma unroll
        for (int o = 1; o <= 2; o <<= 1) {
            mx0 = fmaxf(mx0, __shfl_xor_sync(0xffffffffu, mx0, o));
            mx1 = fmaxf(mx1, __shfl_xor_sync(0xffffffffu, mx1, o));
        }
        if ((lane & 3) == 0) {
            sm[ORED + wnh * 64 + wm + rq]     = mx0;
            sm[ORED + wnh * 64 + wm + rq + 8] = mx1;
        }
        __syncthreads();

        const float mo0 = sm[OM_ + wm + rq];
        const float mo1 = sm[OM_ + wm + rq + 8];
        const float mn0 = fmaxf(mo0, fmaxf(sm[ORED + wm + rq],     sm[ORED + 64 + wm + rq]));
        const float mn1 = fmaxf(mo1, fmaxf(sm[ORED + wm + rq + 8], sm[ORED + 64 + wm + rq + 8]));
        const float al0 = __expf(mo0 - mn0);
        const float al1 = __expf(mo1 - mn1);
#pragma unroll
        for (int nf = 0; nf < 8; nf++) {
            accO[nf][0] *= al0; accO[nf][1] *= al0;
            accO[nf][2] *= al1; accO[nf][3] *= al1;
        }
        float s0 = 0.f, s1 = 0.f;
#pragma unroll
        for (int nf = 0; nf < 4; nf++) {
            const float p0 = __expf(accS[nf][0] - mn0);
            const float p1 = __expf(accS[nf][1] - mn0);
            const float p2 = __expf(accS[nf][2] - mn1);
            const float p3 = __expf(accS[nf][3] - mn1);
            s0 += p0 + p1; s1 += p2 + p3;
            const int pc = wn + 8 * nf + 2 * (lane & 3);
            *(float2*)&sm[OP_ + (wm + rq)     * PST + pc] = make_float2(tf32r(p0), tf32r(p1));
            *(float2*)&sm[OP_ + (wm + rq + 8) * PST + pc] = make_float2(tf32r(p2), tf32r(p3));
        }
#pragma unroll
        for (int o = 1; o <= 2; o <<= 1) {
            s0 += __shfl_xor_sync(0xffffffffu, s0, o);
            s1 += __shfl_xor_sync(0xffffffffu, s1, o);
        }
        if ((lane & 3) == 0) {
            sm[OSUM + wnh * 64 + wm + rq]     = s0;
            sm[OSUM + wnh * 64 + wm + rq + 8] = s1;
        }
        __syncthreads();

        if (w < 4 && (lane & 3) == 0) {
            int r = wm + rq;
            sm[OL_ + r] = sm[OL_ + r] * al0 + sm[OSUM + r] + sm[OSUM + 64 + r];
            sm[OM_ + r] = mn0;
            r += 8;
            sm[OL_ + r] = sm[OL_ + r] * al1 + sm[OSUM + r] + sm[OSUM + 64 + r];
            sm[OM_ + r] = mn1;
        }

#pragma unroll
        for (int ks = 0; ks < 8; ks++) {
            unsigned pf[4];
            {
                const int row = wm + (lane & 7) + ((lane >> 3) & 1) * 8;
                const uint32_t addr = sb + 4u * (unsigned)(OP_ + row * PST)
                                    + 16u * (unsigned)(2 * ks + (lane >> 4));
                ldsm4(pf[0], pf[1], pf[2], pf[3], addr);
            }
            const int kv0 = ks * 8 + (lane & 3);
            const float* v0p = &sm[OV_ + kv0 * VST + wn2 + (lane >> 2)];
            const float* v1p = v0p + 4 * VST;
#pragma unroll
            for (int nf = 0; nf < 8; nf++) {
                unsigned bv[2];
                bv[0] = __float_as_uint(v0p[8 * nf]);
                bv[1] = __float_as_uint(v1p[8 * nf]);
                mma_tf32(accO[nf], pf, bv);
            }
        }
    }

    __syncthreads();
    const float li0 = 1.f / sm[OL_ + wm + rq];
    const float li1 = 1.f / sm[OL_ + wm + rq + 8];
    const size_t obase = ((size_t)(b * S_ + qt * 64)) * H_ + hh * HD_;
#pragma unroll
    for (int nf = 0; nf < 8; nf++) {
        const int col = wn2 + 8 * nf + 2 * (lane & 3);
        float* op0 = ctx + obase + (size_t)(wm + rq) * H_ + col;
        float* op1 = ctx + obase + (size_t)(wm + rq + 8) * H_ + col;
        *(float2*)op0 = make_float2(tf32r(accO[nf][0] * li0), tf32r(accO[nf][1] * li0));
        *(float2*)op1 = make_float2(tf32r(accO[nf][2] * li1), tf32r(accO[nf][3] * li1));
    }
}

// ---------------- router ---------------------------------------------------
__global__ void zero_counts_kernel(int* c)
{
    if (threadIdx.x < E_) c[threadIdx.x] = 0;
}

__global__ void router_kernel(const float* __restrict__ xn, const float* __restrict__ rw,
                              int* __restrict__ counts, int* __restrict__ tok,
                              int* __restrict__ aid, float* __restrict__ coef)
{
    const int t = blockIdx.x;
    const int tid = threadIdx.x;
    float a[8] = {0.f,0.f,0.f,0.f,0.f,0.f,0.f,0.f};
    const float* xr = xn + (size_t)t * H_;
    for (int kk = tid; kk < H_; kk += 256) {
        const float xv = xr[kk];
        float4 r0 = *(const float4*)(rw + kk * 8);
        float4 r1 = *(const float4*)(rw + kk * 8 + 4);
        a[0] += xv * r0.x; a[1] += xv * r0.y; a[2] += xv * r0.z; a[3] += xv * r0.w;
        a[4] += xv * r1.x; a[5] += xv * r1.y; a[6] += xv * r1.z; a[7] += xv * r1.w;
    }
#pragma unroll
    for (int o = 16; o > 0; o >>= 1)
#pragma unroll
        for (int e = 0; e < 8; e++) a[e] += __shfl_down_sync(0xffffffffu, a[e], o);
    __shared__ float ws[8][8];
    if ((tid & 31) == 0)
#pragma unroll
        for (int e = 0; e < 8; e++) ws[tid >> 5][e] = a[e];
    __syncthreads();
    if (tid == 0) {
        float lg[8];
#pragma unroll
        for (int e = 0; e < 8; e++) {
            float s = 0.f;
#pragma unroll
            for (int w = 0; w < 8; w++) s += ws[w][e];
            lg[e] = s;
        }
        int i1 = 0;
#pragma unroll
        for (int e = 1; e < 8; e++) if (lg[e] > lg[i1]) i1 = e;
        int i2 = (i1 == 0) ? 1 : 0;
#pragma unroll
        for (int e = 0; e < 8; e++) if (e != i1 && lg[e] > lg[i2]) i2 = e;
        const float ex = expf(lg[i2] - lg[i1]);
        const float c1 = 1.f / (1.f + ex);
        const float c2 = ex / (1.f + ex);
        int s1 = atomicAdd(&counts[i1], 1);
        tok[i1 * T_ + s1] = t; aid[i1 * T_ + s1] = 2 * t;     coef[i1 * T_ + s1] = c1;
        int s2 = atomicAdd(&counts[i2], 1);
        tok[i2 * T_ + s2] = t; aid[i2 * T_ + s2] = 2 * t + 1; coef[i2 * T_ + s2] = c2;
    }
}

// ------- fused SiLU*gate: a13 [8192][4096] -> a1 [8192][2048] (tf32) -------
__global__ void silu_mul_kernel(const float* __restrict__ a13, float* __restrict__ a1)
{
    const int i = blockIdx.x * blockDim.x + threadIdx.x;   // over 8192*512
    const int r = i >> 9, c4 = (i & 511) * 4;
    const float4 g4 = *(const float4*)&a13[(size_t)r * 4096 + c4];
    const float4 u4 = *(const float4*)&a13[(size_t)r * 4096 + 2048 + c4];
    float4 o;
    o.x = tf32r((g4.x / (1.f + __expf(-g4.x))) * u4.x);
    o.y = tf32r((g4.y / (1.f + __expf(-g4.y))) * u4.y);
    o.z = tf32r((g4.z / (1.f + __expf(-g4.z))) * u4.z);
    o.w = tf32r((g4.w / (1.f + __expf(-g4.w))) * u4.w);
    *(float4*)&a1[(size_t)r * 2048 + c4] = o;
}

// ---------------- launcher -------------------------------------------------
extern "C" void kernel_launch(void* const* d_in, const int* in_sizes, int n_in,
                              void* d_out, int out_size)
{
    const float* hidden   = (const float*)d_in[0];
    const int*   pos      = (const int*)  d_in[1];
    const float* rms1_w   = (const float*)d_in[2];
    const float* rms2_w   = (const float*)d_in[3];
    const float* q_w      = (const float*)d_in[4];
    const float* k_w      = (const float*)d_in[5];
    const float* v_w      = (const float*)d_in[6];
    const float* o_w      = (const float*)d_in[7];
    const float* router_w = (const float*)d_in[8];
    const float* w1       = (const float*)d_in[9];
    const float* w2       = (const float*)d_in[10];
    const float* w3       = (const float*)d_in[11];
    float* out = (float*)d_out;

    float *xn, *xnr, *qkv, *ctx, *h1, *a13, *a1, *coef;
    float *wqkvT, *woT, *w13T, *w2T;
    int *cnt, *tokl, *aidl;
    cudaGetSymbolAddress((void**)&xn,    g_xn);
    cudaGetSymbolAddress((void**)&xnr,   g_xnr);
    cudaGetSymbolAddress((void**)&qkv,   g_qkv);
    cudaGetSymbolAddress((void**)&ctx,   g_ctx);
    cudaGetSymbolAddress((void**)&h1,    g_h1);
    cudaGetSymbolAddress((void**)&a13,   g_a13);
    cudaGetSymbolAddress((void**)&a1,    g_a1);
    cudaGetSymbolAddress((void**)&coef,  g_coef);
    cudaGetSymbolAddress((void**)&cnt,   g_cnt);
    cudaGetSymbolAddress((void**)&tokl,  g_tok);
    cudaGetSymbolAddress((void**)&aidl,  g_aid);
    cudaGetSymbolAddress((void**)&wqkvT, g_wqkvT);
    cudaGetSymbolAddress((void**)&woT,   g_woT);
    cudaGetSymbolAddress((void**)&w13T,  g_w13T);
    cudaGetSymbolAddress((void**)&w2T,   g_w2T);

    cudaFuncSetAttribute(mma_gemm, cudaFuncAttributeMaxDynamicSharedMemorySize, MMA_SMEM);
    cudaFuncSetAttribute(flash2_kernel, cudaFuncAttributeMaxDynamicSharedMemorySize, FLASH2_SMEM);

    const dim3 tb(32, 8);
    // 0. weight prep: qkv+o transpose, w1|w3 combined, w2
    wtrans4_kernel<<<dim3(64, 64, 4), tb>>>(q_w, k_w, v_w, o_w, wqkvT, woT);
    wtrans13_kernel<<<dim3(64, 64, 2 * E_), tb>>>(w1, w3, w13T);
    wtrans_kernel<<<dim3(64, 64, E_), tb>>>(w2, w2T);

    // 1. pre-attention rmsnorm (rounded only)
    rmsnorm_kernel<<<T_, 256>>>(hidden, rms1_w, xnr, nullptr, nullptr);
    // 2. fused QKV projection: [T][6144]
    mma_gemm<<<dim3(3 * H_ / 128, T_ / 128, 1), 256, MMA_SMEM>>>(
        xnr, wqkvT, qkv, nullptr, nullptr, nullptr, nullptr, nullptr, T_, 3 * H_, H_, 0);
    // 3. RoPE + tf32-round q/k/v in fused layout
    rope_kernel<<<(T_ * NH_ * 64) / 256, 256>>>(qkv, pos);
    // 4. flash attention (tensor cores)
    flash2_kernel<<<dim3(S_ / 64, NH_, 2), 256, FLASH2_SMEM>>>(qkv, ctx);
    // 5. O projection + residual
    mma_gemm<<<dim3(H_ / 128, T_ / 128, 1), 256, MMA_SMEM>>>(
        ctx, woT, h1, hidden, nullptr, nullptr, nullptr, nullptr, T_, H_, H_, 0);
    // 6. post-attention rmsnorm: rounded + exact (router) + seed out with h1
    rmsnorm_kernel<<<T_, 256>>>(h1, rms2_w, xnr, xn, out);
    // 7. routing
    zero_counts_kernel<<<1, 32>>>(cnt);
    router_kernel<<<T_, 256>>>(xn, router_w, cnt, tokl, aidl, coef);
    // 8. fused expert up-projection (w1|w3): a13 [8192][4096]
    mma_gemm<<<dim3(2 * I_ / 128, T_ / 128, E_), 256, MMA_SMEM>>>(
        xnr, w13T, a13, nullptr, cnt, tokl, aidl, nullptr, T_, 2 * I_, H_, 1);
    // 9. fused activation -> a1 [8192][2048]
    silu_mul_kernel<<<(2 * T_ * I_ / 4) / 256, 256>>>(a13, a1);
    // 10. down projection: atomic scatter coeff * result into out (= h1 + moe)
    mma_gemm<<<dim3(H_ / 128, T_ / 128, E_), 256, MMA_SMEM>>>(
        a1, w2T, out, nullptr, cnt, aidl, tokl, coef, T_, H_, I_, 2);
}